// round 1
// baseline (speedup 1.0000x reference)
#include <cuda_runtime.h>
#include <math.h>

#define DIM 256
#define HEADS 8
#define HEAD_DIM 32
#define WIN 64          // tokens per window
#define N1 128          // queries per window
#define NWIN 2048       // total windows
#define SCALE 0.17677669529663687f   // 32^-0.5
#define LDW 257         // padded leading dim for 64x256 smem tiles

// ---------------- device scratch (allocation-free rule: __device__ globals) ---
__device__ float g_q[HEADS * N1 * HEAD_DIM];     // [h][q][d] * SCALE
__device__ float g_bias[HEADS * WIN * WIN];      // [h][q%64][k]
__device__ float g_outpre[(size_t)NWIN * N1 * DIM];  // 256 MB pre-projection

// ---------------- prep kernels ----------------
__global__ void prep_q(const float* __restrict__ embeds) {
    int i = blockIdx.x * blockDim.x + threadIdx.x;
    if (i >= HEADS * N1 * HEAD_DIM) return;
    int d = i & 31, q = (i >> 5) & 127, h = i >> 12;
    g_q[i] = embeds[q * DIM + h * HEAD_DIM + d] * SCALE;
}

__global__ void prep_bias(const float* __restrict__ rpb) {
    int i = blockIdx.x * blockDim.x + threadIdx.x;
    if (i >= HEADS * WIN * WIN) return;
    int k = i & 63, qq = (i >> 6) & 63, h = i >> 12;
    int i1 = qq >> 3, j1 = qq & 7, i2 = k >> 3, j2 = k & 7;
    int idx = (i1 - i2 + 7) * 15 + (j1 - j2 + 7);
    g_bias[i] = rpb[idx * HEADS + h];
}

// ---------------- fused window kernel: load + KV GEMM + attention -------------
// smem layout (floats):
//  win_s [64][257] @ 0       (16448)
//  k_s   [64][257] @ 16448   (16448)
//  v_s   [64][257] @ 32896   (16448)
//  ws    [32][132] @ 49344   (4224)
//  p_s   [8][64]   @ 53568   (512)
// total 54080 floats = 216320 bytes
extern __shared__ float smem[];

__global__ __launch_bounds__(256, 1)
void win_attn(const float* __restrict__ x,
              const float* __restrict__ kvw,
              const float* __restrict__ kvb) {
    float* win_s = smem;
    float* k_s   = smem + 16448;
    float* v_s   = smem + 32896;
    float* ws    = smem + 49344;
    float* p_s   = smem + 53568;

    const int tid = threadIdx.x;
    const int bw  = blockIdx.x;
    const int b   = bw >> 10;
    const int wr  = (bw >> 5) & 31;
    const int wc  = bw & 31;

    // ---- load window tile [64 tokens][256 ch], coalesced float4 ----
    {
        const float4* xv = (const float4*)(x +
            ((size_t)((b * 256 + wr * 8) * 256 + wc * 8)) * 256);
        #pragma unroll
        for (int i = 0; i < 16; i++) {
            int idx = tid + i * 256;        // 0..4095
            int t  = idx >> 6;              // token 0..63
            int c4 = idx & 63;              // float4 index in channel dim
            int r  = t >> 3, cc = t & 7;
            float4 v = xv[r * 16384 + cc * 64 + c4];
            float* dst = win_s + t * LDW + c4 * 4;
            dst[0] = v.x; dst[1] = v.y; dst[2] = v.z; dst[3] = v.w;
        }
    }

    const int tx = tid & 15, ty = tid >> 4;

    // ---- KV GEMM: C[64][512] = win @ kv_w^T + kv_b ----
    // 4 column passes of 128; per thread: 4 rows x 8 cols
    for (int jpass = 0; jpass < 4; jpass++) {
        float acc[4][8];
        #pragma unroll
        for (int i = 0; i < 4; i++)
            #pragma unroll
            for (int j = 0; j < 8; j++) acc[i][j] = 0.f;

        for (int kc = 0; kc < 8; kc++) {
            __syncthreads();   // also covers win_s load on first iteration
            // stage ws[cc(32)][jj(128)] from kv_w[jpass*128+jj][kc*32+cc]
            #pragma unroll
            for (int i = 0; i < 4; i++) {
                int idx = tid + i * 256;    // 0..1023
                int jj = idx >> 3, c4 = idx & 7;
                float4 w = *(const float4*)(kvw +
                    (size_t)(jpass * 128 + jj) * 256 + kc * 32 + c4 * 4);
                ws[(c4 * 4 + 0) * 132 + jj] = w.x;
                ws[(c4 * 4 + 1) * 132 + jj] = w.y;
                ws[(c4 * 4 + 2) * 132 + jj] = w.z;
                ws[(c4 * 4 + 3) * 132 + jj] = w.w;
            }
            __syncthreads();
            #pragma unroll
            for (int cc = 0; cc < 32; cc++) {
                int c = kc * 32 + cc;
                float a0 = win_s[(ty * 4 + 0) * LDW + c];
                float a1 = win_s[(ty * 4 + 1) * LDW + c];
                float a2 = win_s[(ty * 4 + 2) * LDW + c];
                float a3 = win_s[(ty * 4 + 3) * LDW + c];
                const float4* wrow = (const float4*)(ws + cc * 132 + tx * 8);
                float4 w0 = wrow[0], w1 = wrow[1];
                float wv[8] = {w0.x, w0.y, w0.z, w0.w, w1.x, w1.y, w1.z, w1.w};
                #pragma unroll
                for (int j = 0; j < 8; j++) {
                    acc[0][j] += a0 * wv[j];
                    acc[1][j] += a1 * wv[j];
                    acc[2][j] += a2 * wv[j];
                    acc[3][j] += a3 * wv[j];
                }
            }
        }
        // write to k_s (j<256) / v_s (j>=256) with bias
        #pragma unroll
        for (int j = 0; j < 8; j++) {
            int jg = jpass * 128 + tx * 8 + j;
            float bias = kvb[jg];
            float* dst = (jg < 256) ? (k_s + jg) : (v_s + (jg - 256));
            #pragma unroll
            for (int i = 0; i < 4; i++)
                dst[(ty * 4 + i) * LDW] = acc[i][j] + bias;
        }
    }
    __syncthreads();

    // ---- attention: each warp owns 16 query rows ----
    const int w = tid >> 5, lane = tid & 31;
    for (int h = 0; h < HEADS; h++) {
        const float* kr0 = k_s + lane * LDW + h * HEAD_DIM;
        const float* kr1 = k_s + (lane + 32) * LDW + h * HEAD_DIM;
        const float* vc  = v_s + h * HEAD_DIM + lane;
        for (int qi = 0; qi < 16; qi++) {
            int q = w * 16 + qi;
            float qreg = g_q[((h * N1) + q) * HEAD_DIM + lane];
            float s0 = g_bias[h * 4096 + (q & 63) * 64 + lane];
            float s1 = g_bias[h * 4096 + (q & 63) * 64 + lane + 32];
            #pragma unroll
            for (int d = 0; d < 32; d++) {
                float qd = __shfl_sync(0xffffffffu, qreg, d);
                s0 += qd * kr0[d];
                s1 += qd * kr1[d];
            }
            // softmax over 64 (2 values per lane, warp-wide)
            float m = fmaxf(s0, s1);
            #pragma unroll
            for (int o = 16; o; o >>= 1)
                m = fmaxf(m, __shfl_xor_sync(0xffffffffu, m, o));
            float e0 = __expf(s0 - m), e1 = __expf(s1 - m);
            float sum = e0 + e1;
            #pragma unroll
            for (int o = 16; o; o >>= 1)
                sum += __shfl_xor_sync(0xffffffffu, sum, o);
            float inv = 1.0f / sum;
            p_s[w * 64 + lane]      = e0 * inv;
            p_s[w * 64 + lane + 32] = e1 * inv;
            __syncwarp();
            // O row: lane = head dim
            float o_acc = 0.f;
            const float* pp = p_s + w * 64;
            #pragma unroll
            for (int k = 0; k < 64; k++)
                o_acc += pp[k] * vc[k * LDW];
            g_outpre[((size_t)bw * N1 + q) * DIM + h * HEAD_DIM + lane] = o_acc;
            __syncwarp();
        }
    }
}

// ---------------- projection GEMM: out = outpre @ proj_w^T + proj_b ----------
__global__ __launch_bounds__(256)
void proj_kernel(const float* __restrict__ pw,
                 const float* __restrict__ pb,
                 float* __restrict__ out) {
    __shared__ float At[32 * 132];
    __shared__ float Pw[32 * 132];
    const int tid = threadIdx.x, tx = tid & 15, ty = tid >> 4;
    const size_t row0 = (size_t)blockIdx.x * 128;

    for (int pass = 0; pass < 2; pass++) {
        float acc[8][8];
        #pragma unroll
        for (int i = 0; i < 8; i++)
            #pragma unroll
            for (int j = 0; j < 8; j++) acc[i][j] = 0.f;

        for (int kc = 0; kc < 8; kc++) {
            __syncthreads();
            #pragma unroll
            for (int i = 0; i < 4; i++) {
                int idx = tid + i * 256;        // 0..1023
                int r = idx >> 3, c4 = idx & 7;
                float4 a = *(const float4*)(g_outpre +
                    (row0 + r) * 256 + kc * 32 + c4 * 4);
                At[(c4 * 4 + 0) * 132 + r] = a.x;
                At[(c4 * 4 + 1) * 132 + r] = a.y;
                At[(c4 * 4 + 2) * 132 + r] = a.z;
                At[(c4 * 4 + 3) * 132 + r] = a.w;
                float4 wv = *(const float4*)(pw +
                    (size_t)(pass * 128 + r) * 256 + kc * 32 + c4 * 4);
                Pw[(c4 * 4 + 0) * 132 + r] = wv.x;
                Pw[(c4 * 4 + 1) * 132 + r] = wv.y;
                Pw[(c4 * 4 + 2) * 132 + r] = wv.z;
                Pw[(c4 * 4 + 3) * 132 + r] = wv.w;
            }
            __syncthreads();
            #pragma unroll
            for (int cc = 0; cc < 32; cc++) {
                const float4* ar = (const float4*)(At + cc * 132 + ty * 8);
                float4 a0 = ar[0], a1 = ar[1];
                const float4* wr = (const float4*)(Pw + cc * 132 + tx * 8);
                float4 w0 = wr[0], w1 = wr[1];
                float av[8] = {a0.x, a0.y, a0.z, a0.w, a1.x, a1.y, a1.z, a1.w};
                float wv[8] = {w0.x, w0.y, w0.z, w0.w, w1.x, w1.y, w1.z, w1.w};
                #pragma unroll
                for (int i = 0; i < 8; i++)
                    #pragma unroll
                    for (int j = 0; j < 8; j++)
                        acc[i][j] += av[i] * wv[j];
            }
        }
        // epilogue: thread owns 8 consecutive oc -> coalesced float4 stores
        int oc0 = pass * 128 + tx * 8;
        float b0 = pb[oc0 + 0], b1 = pb[oc0 + 1], b2 = pb[oc0 + 2], b3 = pb[oc0 + 3];
        float b4 = pb[oc0 + 4], b5 = pb[oc0 + 5], b6 = pb[oc0 + 6], b7 = pb[oc0 + 7];
        #pragma unroll
        for (int i = 0; i < 8; i++) {
            size_t row = row0 + ty * 8 + i;
            float4 v0 = make_float4(acc[i][0] + b0, acc[i][1] + b1,
                                    acc[i][2] + b2, acc[i][3] + b3);
            float4 v1 = make_float4(acc[i][4] + b4, acc[i][5] + b5,
                                    acc[i][6] + b6, acc[i][7] + b7);
            float4* dst = (float4*)(out + row * 256 + oc0);
            dst[0] = v0;
            dst[1] = v1;
        }
    }
}

// ---------------- launch ----------------
static const float* find_by_size(void* const* d_in, const int* in_sizes,
                                 int n_in, int want) {
    for (int i = 0; i < n_in; i++)
        if (in_sizes[i] == want) return (const float*)d_in[i];
    return nullptr;
}

extern "C" void kernel_launch(void* const* d_in, const int* in_sizes, int n_in,
                              void* d_out, int out_size) {
    const float* embeds = find_by_size(d_in, in_sizes, n_in, 1 * 128 * 256);
    const float* x      = find_by_size(d_in, in_sizes, n_in, 2 * 256 * 256 * 256);
    const float* rpb    = find_by_size(d_in, in_sizes, n_in, 225 * 8);
    const float* kvw    = find_by_size(d_in, in_sizes, n_in, 512 * 256);
    const float* kvb    = find_by_size(d_in, in_sizes, n_in, 512);
    const float* pw     = find_by_size(d_in, in_sizes, n_in, 256 * 256);
    const float* pb     = find_by_size(d_in, in_sizes, n_in, 256);
    float* out = (float*)d_out;

    prep_q<<<(HEADS * N1 * HEAD_DIM + 255) / 256, 256>>>(embeds);
    prep_bias<<<(HEADS * WIN * WIN + 255) / 256, 256>>>(rpb);

    cudaFuncSetAttribute(win_attn,
                         cudaFuncAttributeMaxDynamicSharedMemorySize, 216320);
    win_attn<<<NWIN, 256, 216320>>>(x, kvw, kvb);

    proj_kernel<<<NWIN, 256>>>(pw, pb, out);
}

// round 2
// speedup vs baseline: 2.6266x; 2.6266x over previous
#include <cuda_runtime.h>
#include <math.h>
#include <stdint.h>

#define DIM 256
#define HEADS 8
#define WIN 64
#define N1 128
#define NWIN 2048
#define SCALE 0.17677669529663687f
#define LDW 264

// ---------------- device scratch ----------------
__device__ float g_qhi[HEADS * N1 * 32];
__device__ float g_qlo[HEADS * N1 * 32];
__device__ float g_bias[HEADS * WIN * WIN];
__device__ float g_kvw_hi[512 * 256];
__device__ float g_kvw_lo[512 * 256];
__device__ float g_pw_hi[256 * 256];
__device__ float g_pw_lo[256 * 256];
__device__ float g_outpre[(size_t)NWIN * N1 * DIM];

// ---------------- tf32 helpers ----------------
__device__ __forceinline__ uint32_t f2tf(float x) {
    uint32_t r;
    asm("cvt.rna.tf32.f32 %0, %1;" : "=r"(r) : "f"(x));
    return r;
}
__device__ __forceinline__ void split_tf32(float x, uint32_t& hi, uint32_t& lo) {
    hi = f2tf(x);
    lo = f2tf(x - __uint_as_float(hi));
}
__device__ __forceinline__ void mma8(float c[4], const uint32_t a[4], const uint32_t b[2]) {
    asm volatile(
        "mma.sync.aligned.m16n8k8.row.col.f32.tf32.tf32.f32 "
        "{%0,%1,%2,%3},{%4,%5,%6,%7},{%8,%9},{%0,%1,%2,%3};\n"
        : "+f"(c[0]), "+f"(c[1]), "+f"(c[2]), "+f"(c[3])
        : "r"(a[0]), "r"(a[1]), "r"(a[2]), "r"(a[3]), "r"(b[0]), "r"(b[1]));
}
#define FU(x) __float_as_uint(x)

// ---------------- prep kernels ----------------
__global__ void prep_q(const float* __restrict__ e) {
    int i = blockIdx.x * blockDim.x + threadIdx.x;
    if (i >= HEADS * N1 * 32) return;
    int d = i & 31, q = (i >> 5) & 127, h = i >> 12;
    float v = e[q * DIM + h * 32 + d] * SCALE;
    uint32_t hi, lo;
    split_tf32(v, hi, lo);
    g_qhi[i] = __uint_as_float(hi);
    g_qlo[i] = __uint_as_float(lo);
}

__global__ void prep_bias(const float* __restrict__ rpb) {
    int i = blockIdx.x * blockDim.x + threadIdx.x;
    if (i >= HEADS * WIN * WIN) return;
    int k = i & 63, qq = (i >> 6) & 63, h = i >> 12;
    int i1 = qq >> 3, j1 = qq & 7, i2 = k >> 3, j2 = k & 7;
    int idx = (i1 - i2 + 7) * 15 + (j1 - j2 + 7);
    g_bias[i] = rpb[idx * HEADS + h];
}

__global__ void prep_w(const float* __restrict__ kvw, const float* __restrict__ pw) {
    int i = blockIdx.x * blockDim.x + threadIdx.x;
    uint32_t hi, lo;
    if (i < 512 * 256) {
        split_tf32(kvw[i], hi, lo);
        g_kvw_hi[i] = __uint_as_float(hi);
        g_kvw_lo[i] = __uint_as_float(lo);
    } else if (i < 512 * 256 + 256 * 256) {
        int j = i - 512 * 256;
        split_tf32(pw[j], hi, lo);
        g_pw_hi[j] = __uint_as_float(hi);
        g_pw_lo[j] = __uint_as_float(lo);
    }
}

// ---------------- fused window kernel ----------------
// dynamic smem (floats):
//  win_s [64][264] @ 0        (16896)   (aliased by pbuf in attention phase)
//  k_s   [64][264] @ 16896    (16896)
//  v_s   [64][264] @ 33792    (16896)
//  wshi  [8][264]  @ 50688    (2112)
//  wslo  [8][264]  @ 52800    (2112)
//  kvb_s [512]     @ 54912    (512)
// total 55424 floats = 221696 bytes
extern __shared__ float smem[];

__global__ __launch_bounds__(256, 1)
void win_attn(const float* __restrict__ x, const float* __restrict__ kvb) {
    float* win_s = smem;
    float* k_s   = smem + 16896;
    float* v_s   = smem + 33792;
    float* wshi  = smem + 50688;
    float* wslo  = smem + 52800;
    float* kvb_s = smem + 54912;
    float* pbuf  = smem;               // alias of win_s after KV phase

    const int tid = threadIdx.x;
    const int bw  = blockIdx.x;
    const int b   = bw >> 10;
    const int wr  = (bw >> 5) & 31;
    const int wc  = bw & 31;
    const int w    = tid >> 5;
    const int lane = tid & 31;
    const int g    = lane >> 2;
    const int t    = lane & 3;

    // ---- load window tile [64 tok][256 ch] ----
    {
        const float4* xv = (const float4*)(x +
            ((size_t)((b * 256 + wr * 8) * 256 + wc * 8)) * 256);
        #pragma unroll
        for (int i = 0; i < 16; i++) {
            int idx = tid + i * 256;
            int tok = idx >> 6, c4 = idx & 63;
            int r = tok >> 3, cc = tok & 7;
            float4 v = xv[r * 16384 + cc * 64 + c4];
            float* dst = win_s + tok * LDW + c4 * 4;
            dst[0] = v.x; dst[1] = v.y; dst[2] = v.z; dst[3] = v.w;
        }
        kvb_s[tid]       = kvb[tid];
        kvb_s[tid + 256] = kvb[tid + 256];
    }

    const int wm = (w >> 1) * 16;   // warp M offset (4 groups of 16 rows)
    const int wn = (w & 1) * 128;   // warp N offset within 256-wide pass

    // ---- KV GEMM: [64 x 512] = win @ kv_w^T, 3xTF32 ----
    for (int p = 0; p < 2; p++) {
        float acc[16][4];
        #pragma unroll
        for (int j = 0; j < 16; j++)
            #pragma unroll
            for (int e = 0; e < 4; e++) acc[j][e] = 0.f;

        for (int kc = 0; kc < 32; kc++) {
            __syncthreads();
            // stage kv_w hi/lo tile [8 k][256 n]
            #pragma unroll
            for (int i = 0; i < 2; i++) {
                int idx = tid + i * 256;
                int n = idx >> 1, kq = idx & 1;
                size_t goff = (size_t)(p * 256 + n) * 256 + kc * 8 + kq * 4;
                float4 h4 = *(const float4*)(g_kvw_hi + goff);
                float4 l4 = *(const float4*)(g_kvw_lo + goff);
                wshi[(kq * 4 + 0) * LDW + n] = h4.x;
                wshi[(kq * 4 + 1) * LDW + n] = h4.y;
                wshi[(kq * 4 + 2) * LDW + n] = h4.z;
                wshi[(kq * 4 + 3) * LDW + n] = h4.w;
                wslo[(kq * 4 + 0) * LDW + n] = l4.x;
                wslo[(kq * 4 + 1) * LDW + n] = l4.y;
                wslo[(kq * 4 + 2) * LDW + n] = l4.z;
                wslo[(kq * 4 + 3) * LDW + n] = l4.w;
            }
            __syncthreads();

            int k0 = kc * 8;
            uint32_t ahi[4], alo[4];
            split_tf32(win_s[(wm + g) * LDW + k0 + t],         ahi[0], alo[0]);
            split_tf32(win_s[(wm + g + 8) * LDW + k0 + t],     ahi[1], alo[1]);
            split_tf32(win_s[(wm + g) * LDW + k0 + t + 4],     ahi[2], alo[2]);
            split_tf32(win_s[(wm + g + 8) * LDW + k0 + t + 4], ahi[3], alo[3]);

            #pragma unroll
            for (int j = 0; j < 16; j++) {
                int n = wn + 8 * j + g;
                uint32_t bhi[2] = { FU(wshi[t * LDW + n]), FU(wshi[(t + 4) * LDW + n]) };
                uint32_t blo[2] = { FU(wslo[t * LDW + n]), FU(wslo[(t + 4) * LDW + n]) };
                mma8(acc[j], ahi, bhi);
                mma8(acc[j], ahi, blo);
                mma8(acc[j], alo, bhi);
            }
        }
        // write K (p=0) / V (p=1) tiles with bias
        float* dst = p ? v_s : k_s;
        #pragma unroll
        for (int j = 0; j < 16; j++) {
            int c = wn + 8 * j + 2 * t;
            float b0 = kvb_s[p * 256 + c], b1 = kvb_s[p * 256 + c + 1];
            int r0 = wm + g;
            dst[r0 * LDW + c]           = acc[j][0] + b0;
            dst[r0 * LDW + c + 1]       = acc[j][1] + b1;
            dst[(r0 + 8) * LDW + c]     = acc[j][2] + b0;
            dst[(r0 + 8) * LDW + c + 1] = acc[j][3] + b1;
        }
    }
    __syncthreads();

    // ---- attention: warp w owns query rows 16w..16w+15, all heads ----
    float* pw_ = pbuf + w * 1152;   // per-warp 16x72 P tile
    const int q0 = w * 16 + g;

    for (int h = 0; h < HEADS; h++) {
        // preload Q fragments (hi/lo), 8 k-positions per row, 2 rows
        float qh[2][8], ql[2][8];
        const float* qbh = g_qhi + h * 4096;
        const float* qbl = g_qlo + h * 4096;
        #pragma unroll
        for (int rr = 0; rr < 2; rr++) {
            int q = q0 + rr * 8;
            #pragma unroll
            for (int kk = 0; kk < 8; kk++) {
                qh[rr][kk] = __ldg(qbh + q * 32 + t + kk * 4);
                ql[rr][kk] = __ldg(qbl + q * 32 + t + kk * 4);
            }
        }

        // S = Q K^T + bias  (init acc with bias)
        float sacc[8][4];
        {
            const float* bb = g_bias + h * 4096;
            int r0m = q0 & 63, r1m = (q0 + 8) & 63;
            #pragma unroll
            for (int j = 0; j < 8; j++) {
                int key = 8 * j + 2 * t;
                sacc[j][0] = __ldg(bb + r0m * 64 + key);
                sacc[j][1] = __ldg(bb + r0m * 64 + key + 1);
                sacc[j][2] = __ldg(bb + r1m * 64 + key);
                sacc[j][3] = __ldg(bb + r1m * 64 + key + 1);
            }
        }
        #pragma unroll
        for (int ks = 0; ks < 4; ks++) {
            uint32_t ahi[4] = { FU(qh[0][2*ks]), FU(qh[1][2*ks]), FU(qh[0][2*ks+1]), FU(qh[1][2*ks+1]) };
            uint32_t alo[4] = { FU(ql[0][2*ks]), FU(ql[1][2*ks]), FU(ql[0][2*ks+1]), FU(ql[1][2*ks+1]) };
            #pragma unroll
            for (int j = 0; j < 8; j++) {
                int key = 8 * j + g;
                uint32_t bhi[2], blo[2];
                split_tf32(k_s[key * LDW + h * 32 + 8 * ks + t],     bhi[0], blo[0]);
                split_tf32(k_s[key * LDW + h * 32 + 8 * ks + t + 4], bhi[1], blo[1]);
                mma8(sacc[j], ahi, bhi);
                mma8(sacc[j], ahi, blo);
                mma8(sacc[j], alo, bhi);
            }
        }

        // softmax over 64 keys; row r0 -> (c0,c1), row r0+8 -> (c2,c3);
        // each row is shared by the 4 threads of a group -> shfl_xor 1,2
        float m0 = -1e30f, m1 = -1e30f;
        #pragma unroll
        for (int j = 0; j < 8; j++) {
            m0 = fmaxf(m0, fmaxf(sacc[j][0], sacc[j][1]));
            m1 = fmaxf(m1, fmaxf(sacc[j][2], sacc[j][3]));
        }
        m0 = fmaxf(m0, __shfl_xor_sync(0xffffffffu, m0, 1));
        m0 = fmaxf(m0, __shfl_xor_sync(0xffffffffu, m0, 2));
        m1 = fmaxf(m1, __shfl_xor_sync(0xffffffffu, m1, 1));
        m1 = fmaxf(m1, __shfl_xor_sync(0xffffffffu, m1, 2));
        float s0 = 0.f, s1 = 0.f;
        #pragma unroll
        for (int j = 0; j < 8; j++) {
            sacc[j][0] = __expf(sacc[j][0] - m0); s0 += sacc[j][0];
            sacc[j][1] = __expf(sacc[j][1] - m0); s0 += sacc[j][1];
            sacc[j][2] = __expf(sacc[j][2] - m1); s1 += sacc[j][2];
            sacc[j][3] = __expf(sacc[j][3] - m1); s1 += sacc[j][3];
        }
        s0 += __shfl_xor_sync(0xffffffffu, s0, 1);
        s0 += __shfl_xor_sync(0xffffffffu, s0, 2);
        s1 += __shfl_xor_sync(0xffffffffu, s1, 1);
        s1 += __shfl_xor_sync(0xffffffffu, s1, 2);
        float inv0 = 1.0f / s0, inv1 = 1.0f / s1;

        // store P tile [16][72]
        #pragma unroll
        for (int j = 0; j < 8; j++) {
            int c = 8 * j + 2 * t;
            pw_[g * 72 + c]           = sacc[j][0] * inv0;
            pw_[g * 72 + c + 1]       = sacc[j][1] * inv0;
            pw_[(g + 8) * 72 + c]     = sacc[j][2] * inv1;
            pw_[(g + 8) * 72 + c + 1] = sacc[j][3] * inv1;
        }
        __syncwarp();

        // O = P @ V   (M=16, N=32, K=64)
        float oacc[4][4];
        #pragma unroll
        for (int j = 0; j < 4; j++)
            #pragma unroll
            for (int e = 0; e < 4; e++) oacc[j][e] = 0.f;

        #pragma unroll
        for (int ks = 0; ks < 8; ks++) {
            int k0 = 8 * ks;
            uint32_t ahi[4], alo[4];
            split_tf32(pw_[g * 72 + k0 + t],           ahi[0], alo[0]);
            split_tf32(pw_[(g + 8) * 72 + k0 + t],     ahi[1], alo[1]);
            split_tf32(pw_[g * 72 + k0 + t + 4],       ahi[2], alo[2]);
            split_tf32(pw_[(g + 8) * 72 + k0 + t + 4], ahi[3], alo[3]);
            #pragma unroll
            for (int j = 0; j < 4; j++) {
                int d = h * 32 + 8 * j + g;
                uint32_t bhi[2], blo[2];
                split_tf32(v_s[(k0 + t) * LDW + d],     bhi[0], blo[0]);
                split_tf32(v_s[(k0 + t + 4) * LDW + d], bhi[1], blo[1]);
                mma8(oacc[j], ahi, bhi);
                mma8(oacc[j], ahi, blo);
                mma8(oacc[j], alo, bhi);
            }
        }

        // store O fragment to g_outpre
        size_t base = (size_t)bw * 128 * 256;
        #pragma unroll
        for (int j = 0; j < 4; j++) {
            int c = h * 32 + 8 * j + 2 * t;
            *(float2*)(g_outpre + base + (size_t)q0 * 256 + c) =
                make_float2(oacc[j][0], oacc[j][1]);
            *(float2*)(g_outpre + base + (size_t)(q0 + 8) * 256 + c) =
                make_float2(oacc[j][2], oacc[j][3]);
        }
        __syncwarp();
    }
}

// ---------------- projection GEMM: out = outpre @ proj_w^T + proj_b ----------
__global__ __launch_bounds__(256)
void proj_kernel(const float* __restrict__ pb, float* __restrict__ out) {
    __shared__ float As[128 * 8];
    __shared__ float Bh[8 * 136];
    __shared__ float Bl[8 * 136];

    const int tid = threadIdx.x;
    const int w = tid >> 5, lane = tid & 31, g = lane >> 2, t = lane & 3;
    const size_t m0 = (size_t)(blockIdx.x >> 1) * 128;
    const int n0 = (blockIdx.x & 1) * 128;
    const int wm = (w >> 1) * 32, wn = (w & 1) * 64;

    float acc[2][8][4];
    #pragma unroll
    for (int mt = 0; mt < 2; mt++)
        #pragma unroll
        for (int j = 0; j < 8; j++)
            #pragma unroll
            for (int e = 0; e < 4; e++) acc[mt][j][e] = 0.f;

    for (int kc = 0; kc < 32; kc++) {
        __syncthreads();
        {   // stage A [128 rows][8 k]
            int r = tid >> 1, kq = tid & 1;
            float4 a = *(const float4*)(g_outpre + (m0 + r) * 256 + kc * 8 + kq * 4);
            As[r * 8 + kq * 4 + 0] = a.x;
            As[r * 8 + kq * 4 + 1] = a.y;
            As[r * 8 + kq * 4 + 2] = a.z;
            As[r * 8 + kq * 4 + 3] = a.w;
        }
        {   // stage B hi/lo [8 k][128 n]
            int n = tid >> 1, kq = tid & 1;
            size_t goff = (size_t)(n0 + n) * 256 + kc * 8 + kq * 4;
            float4 h4 = *(const float4*)(g_pw_hi + goff);
            float4 l4 = *(const float4*)(g_pw_lo + goff);
            Bh[(kq * 4 + 0) * 136 + n] = h4.x;
            Bh[(kq * 4 + 1) * 136 + n] = h4.y;
            Bh[(kq * 4 + 2) * 136 + n] = h4.z;
            Bh[(kq * 4 + 3) * 136 + n] = h4.w;
            Bl[(kq * 4 + 0) * 136 + n] = l4.x;
            Bl[(kq * 4 + 1) * 136 + n] = l4.y;
            Bl[(kq * 4 + 2) * 136 + n] = l4.z;
            Bl[(kq * 4 + 3) * 136 + n] = l4.w;
        }
        __syncthreads();

        uint32_t ahi[2][4], alo[2][4];
        #pragma unroll
        for (int mt = 0; mt < 2; mt++) {
            int r = wm + mt * 16 + g;
            split_tf32(As[r * 8 + t],           ahi[mt][0], alo[mt][0]);
            split_tf32(As[(r + 8) * 8 + t],     ahi[mt][1], alo[mt][1]);
            split_tf32(As[r * 8 + t + 4],       ahi[mt][2], alo[mt][2]);
            split_tf32(As[(r + 8) * 8 + t + 4], ahi[mt][3], alo[mt][3]);
        }
        #pragma unroll
        for (int j = 0; j < 8; j++) {
            int n = wn + 8 * j + g;
            uint32_t bhi[2] = { FU(Bh[t * 136 + n]), FU(Bh[(t + 4) * 136 + n]) };
            uint32_t blo[2] = { FU(Bl[t * 136 + n]), FU(Bl[(t + 4) * 136 + n]) };
            #pragma unroll
            for (int mt = 0; mt < 2; mt++) {
                mma8(acc[mt][j], ahi[mt], bhi);
                mma8(acc[mt][j], ahi[mt], blo);
                mma8(acc[mt][j], alo[mt], bhi);
            }
        }
    }

    // epilogue
    #pragma unroll
    for (int mt = 0; mt < 2; mt++)
        #pragma unroll
        for (int j = 0; j < 8; j++) {
            int oc = n0 + wn + 8 * j + 2 * t;
            float b0 = __ldg(pb + oc), b1 = __ldg(pb + oc + 1);
            size_t r = m0 + wm + mt * 16 + g;
            *(float2*)(out + r * 256 + oc) =
                make_float2(acc[mt][j][0] + b0, acc[mt][j][1] + b1);
            *(float2*)(out + (r + 8) * 256 + oc) =
                make_float2(acc[mt][j][2] + b0, acc[mt][j][3] + b1);
        }
}

// ---------------- launch ----------------
static const float* find_by_size(void* const* d_in, const int* in_sizes,
                                 int n_in, int want) {
    for (int i = 0; i < n_in; i++)
        if (in_sizes[i] == want) return (const float*)d_in[i];
    return nullptr;
}

extern "C" void kernel_launch(void* const* d_in, const int* in_sizes, int n_in,
                              void* d_out, int out_size) {
    const float* embeds = find_by_size(d_in, in_sizes, n_in, 128 * 256);
    const float* x      = find_by_size(d_in, in_sizes, n_in, 2 * 256 * 256 * 256);
    const float* rpb    = find_by_size(d_in, in_sizes, n_in, 225 * 8);
    const float* kvw    = find_by_size(d_in, in_sizes, n_in, 512 * 256);
    const float* kvb    = find_by_size(d_in, in_sizes, n_in, 512);
    const float* pw     = find_by_size(d_in, in_sizes, n_in, 256 * 256);
    const float* pb     = find_by_size(d_in, in_sizes, n_in, 256);
    float* out = (float*)d_out;

    prep_q<<<(HEADS * N1 * 32 + 255) / 256, 256>>>(embeds);
    prep_bias<<<(HEADS * WIN * WIN + 255) / 256, 256>>>(rpb);
    prep_w<<<(512 * 256 + 256 * 256 + 255) / 256, 256>>>(kvw, pw);

    cudaFuncSetAttribute(win_attn,
                         cudaFuncAttributeMaxDynamicSharedMemorySize, 221696);
    win_attn<<<NWIN, 256, 221696>>>(x, kvb);

    proj_kernel<<<NWIN * 2, 256>>>(pb, out);
}

// round 3
// speedup vs baseline: 3.4718x; 1.3218x over previous
#include <cuda_runtime.h>
#include <cuda_bf16.h>
#include <math.h>
#include <stdint.h>

#define DIM 256
#define HEADS 8
#define WIN 64
#define N1 128
#define NWIN 2048
#define SCALE 0.17677669529663687f

// ---------------- device scratch ----------------
// packed bf16 pairs: word = {lo16: element 2i, hi16: element 2i+1}
__device__ uint32_t g_qh[HEADS * N1 * 16];   // [h][q][word] (32 dims -> 16 words)
__device__ uint32_t g_ql[HEADS * N1 * 16];
__device__ float    g_bias[HEADS * WIN * WIN];
__device__ uint32_t g_kvwh[512 * 128];       // [n][word]
__device__ uint32_t g_kvwl[512 * 128];
__device__ uint32_t g_pwh[256 * 128];
__device__ uint32_t g_pwl[256 * 128];
__device__ uint32_t g_outh[(size_t)NWIN * 128 * 128];  // [row][word]
__device__ uint32_t g_outl[(size_t)NWIN * 128 * 128];

// ---------------- bf16 split/pack helpers ----------------
__device__ __forceinline__ uint32_t pack2(float x0, float x1, uint32_t& lo) {
    __nv_bfloat16 h0 = __float2bfloat16(x0);
    __nv_bfloat16 h1 = __float2bfloat16(x1);
    __nv_bfloat16 l0 = __float2bfloat16(x0 - __bfloat162float(h0));
    __nv_bfloat16 l1 = __float2bfloat16(x1 - __bfloat162float(h1));
    lo = ((uint32_t)__bfloat16_as_ushort(l1) << 16) | (uint32_t)__bfloat16_as_ushort(l0);
    return ((uint32_t)__bfloat16_as_ushort(h1) << 16) | (uint32_t)__bfloat16_as_ushort(h0);
}

__device__ __forceinline__ void mma16(float c[4], const uint32_t a[4], const uint32_t b[2]) {
    asm volatile(
        "mma.sync.aligned.m16n8k16.row.col.f32.bf16.bf16.f32 "
        "{%0,%1,%2,%3},{%4,%5,%6,%7},{%8,%9},{%0,%1,%2,%3};\n"
        : "+f"(c[0]), "+f"(c[1]), "+f"(c[2]), "+f"(c[3])
        : "r"(a[0]), "r"(a[1]), "r"(a[2]), "r"(a[3]), "r"(b[0]), "r"(b[1]));
}
__device__ __forceinline__ void mma3(float c[4], const uint32_t ah[4], const uint32_t al[4],
                                     const uint32_t bh[2], const uint32_t bl[2]) {
    mma16(c, ah, bh);
    mma16(c, ah, bl);
    mma16(c, al, bh);
}

// ---------------- prep kernels ----------------
__global__ void prep_q(const float* __restrict__ e) {
    int i = blockIdx.x * blockDim.x + threadIdx.x;
    if (i >= HEADS * N1 * 16) return;
    int wd = i & 15, q = (i >> 4) & 127, h = i >> 11;
    float x0 = e[q * DIM + h * 32 + wd * 2] * SCALE;
    float x1 = e[q * DIM + h * 32 + wd * 2 + 1] * SCALE;
    uint32_t lo, hi = pack2(x0, x1, lo);
    g_qh[i] = hi; g_ql[i] = lo;
}

__global__ void prep_bias(const float* __restrict__ rpb) {
    int i = blockIdx.x * blockDim.x + threadIdx.x;
    if (i >= HEADS * WIN * WIN) return;
    int k = i & 63, qq = (i >> 6) & 63, h = i >> 12;
    int i1 = qq >> 3, j1 = qq & 7, i2 = k >> 3, j2 = k & 7;
    int idx = (i1 - i2 + 7) * 15 + (j1 - j2 + 7);
    g_bias[i] = rpb[idx * HEADS + h];
}

__global__ void prep_w(const float* __restrict__ kvw, const float* __restrict__ pw) {
    int i = blockIdx.x * blockDim.x + threadIdx.x;
    if (i < 512 * 128) {
        int wd = i & 127, n = i >> 7;
        uint32_t lo, hi = pack2(kvw[n * 256 + wd * 2], kvw[n * 256 + wd * 2 + 1], lo);
        g_kvwh[i] = hi; g_kvwl[i] = lo;
    } else if (i < 512 * 128 + 256 * 128) {
        int j = i - 512 * 128;
        int wd = j & 127, n = j >> 7;
        uint32_t lo, hi = pack2(pw[n * 256 + wd * 2], pw[n * 256 + wd * 2 + 1], lo);
        g_pwh[j] = hi; g_pwl[j] = lo;
    }
}

// ---------------- fused window kernel ----------------
// smem word layout (uint32 units):
//  ws_hi [8][264] @ 0      (2112)     \  also P region base in attn phase:
//  ws_lo [8][264] @ 2112   (2112)      | per warp 1152 words @ w*1152
//  kvb   [512]f   @ 4224   (512)       | (16*1152=18432 <= 21632)
//  win_h [64][132]@ 4736   (8448)      |
//  win_l [64][132]@ 13184  (8448)     /
//  k_h   [64][132]@ 21632  (8448)
//  k_l   [64][132]@ 30080  (8448)
//  v_h   [32][264]@ 38528  (8448)   (word = {V[2r][d], V[2r+1][d]})
//  v_l   [32][264]@ 46976  (8448)
// total 55424 words = 221696 bytes
#define WS_OFF   0
#define KVB_OFF  4224
#define WIN_OFF  4736
#define K_OFF    21632
#define V_OFF    38528

extern __shared__ uint32_t smw[];

__global__ __launch_bounds__(512, 1)
void win_attn(const float* __restrict__ x, const float* __restrict__ kvb) {
    const int tid  = threadIdx.x;
    const int bw   = blockIdx.x;
    const int b    = bw >> 10;
    const int wr   = (bw >> 5) & 31;
    const int wc   = bw & 31;
    const int w    = tid >> 5;
    const int lane = tid & 31;
    const int g    = lane >> 2;
    const int t    = lane & 3;
    float* kvbf = (float*)(smw + KVB_OFF);

    // ---- load window tile [64 tok][256 ch], split+pack to bf16 pairs ----
    {
        const float4* xv = (const float4*)(x +
            ((size_t)((b * 256 + wr * 8) * 256 + wc * 8)) * 256);
        #pragma unroll
        for (int i = 0; i < 8; i++) {
            int idx = tid + i * 512;            // 0..4095
            int tok = idx >> 6, c4 = idx & 63;
            int r = tok >> 3, cc = tok & 7;
            float4 v = xv[r * 16384 + cc * 64 + c4];
            uint32_t lo0, lo1;
            uint32_t hi0 = pack2(v.x, v.y, lo0);
            uint32_t hi1 = pack2(v.z, v.w, lo1);
            smw[WIN_OFF + tok * 132 + c4 * 2]            = hi0;
            smw[WIN_OFF + tok * 132 + c4 * 2 + 1]        = hi1;
            smw[WIN_OFF + 8448 + tok * 132 + c4 * 2]     = lo0;
            smw[WIN_OFF + 8448 + tok * 132 + c4 * 2 + 1] = lo1;
        }
        kvbf[tid] = kvb[tid];
    }

    const int wm = (w >> 2) * 16;
    const int wn = (w & 3) * 64;

    // ---- KV GEMM: [64 x 512] = win @ kv_w^T, bf16x3, m16n8k16 ----
    for (int p = 0; p < 2; p++) {
        float acc[8][4];
        #pragma unroll
        for (int j = 0; j < 8; j++)
            #pragma unroll
            for (int e = 0; e < 4; e++) acc[j][e] = 0.f;

        for (int kc = 0; kc < 16; kc++) {
            __syncthreads();
            {   // stage kv_w packed tile: [8 words][256 n], hi & lo planes
                int n = tid >> 1, half = tid & 1;
                const uint32_t* src = (half ? g_kvwl : g_kvwh) +
                                      (size_t)(p * 256 + n) * 128 + kc * 8;
                uint32_t* dst = smw + WS_OFF + half * 2112;
                uint4 a4 = *(const uint4*)src;
                uint4 b4 = *(const uint4*)(src + 4);
                dst[0 * 264 + n] = a4.x; dst[1 * 264 + n] = a4.y;
                dst[2 * 264 + n] = a4.z; dst[3 * 264 + n] = a4.w;
                dst[4 * 264 + n] = b4.x; dst[5 * 264 + n] = b4.y;
                dst[6 * 264 + n] = b4.z; dst[7 * 264 + n] = b4.w;
            }
            __syncthreads();

            uint32_t ah[4], al[4];
            int ab  = WIN_OFF + (wm + g) * 132 + kc * 8;
            int ab8 = ab + 8 * 132;
            ah[0] = smw[ab + t];          ah[1] = smw[ab8 + t];
            ah[2] = smw[ab + t + 4];      ah[3] = smw[ab8 + t + 4];
            al[0] = smw[ab + 8448 + t];   al[1] = smw[ab8 + 8448 + t];
            al[2] = smw[ab + 8448 + t + 4]; al[3] = smw[ab8 + 8448 + t + 4];

            #pragma unroll
            for (int j = 0; j < 8; j++) {
                int n2 = wn + 8 * j + g;
                uint32_t bh[2] = { smw[WS_OFF + t * 264 + n2],
                                   smw[WS_OFF + (t + 4) * 264 + n2] };
                uint32_t bl[2] = { smw[WS_OFF + 2112 + t * 264 + n2],
                                   smw[WS_OFF + 2112 + (t + 4) * 264 + n2] };
                mma3(acc[j], ah, al, bh, bl);
            }
        }

        if (p == 0) {
            // K epilogue: pack dim-pairs
            #pragma unroll
            for (int j = 0; j < 8; j++) {
                int c = wn + 8 * j + 2 * t;
                float b0 = kvbf[c], b1 = kvbf[c + 1];
                uint32_t lo, hi;
                hi = pack2(acc[j][0] + b0, acc[j][1] + b1, lo);
                smw[K_OFF + (wm + g) * 132 + (c >> 1)]        = hi;
                smw[K_OFF + 8448 + (wm + g) * 132 + (c >> 1)] = lo;
                hi = pack2(acc[j][2] + b0, acc[j][3] + b1, lo);
                smw[K_OFF + (wm + g + 8) * 132 + (c >> 1)]        = hi;
                smw[K_OFF + 8448 + (wm + g + 8) * 132 + (c >> 1)] = lo;
            }
        } else {
            // V epilogue: pack token-pairs via shfl_xor(4)
            #pragma unroll
            for (int j = 0; j < 8; j++) {
                int c = wn + 8 * j + 2 * t;
                float v0 = acc[j][0] + kvbf[256 + c];
                float v1 = acc[j][1] + kvbf[256 + c + 1];
                float v2 = acc[j][2] + kvbf[256 + c];
                float v3 = acc[j][3] + kvbf[256 + c + 1];
                float o0 = __shfl_xor_sync(0xffffffffu, v0, 4);
                float o1 = __shfl_xor_sync(0xffffffffu, v1, 4);
                float o2 = __shfl_xor_sync(0xffffffffu, v2, 4);
                float o3 = __shfl_xor_sync(0xffffffffu, v3, 4);
                if ((g & 1) == 0) {
                    int rp0 = (wm + g) >> 1, rp1 = rp0 + 4;
                    uint32_t lo, hi;
                    hi = pack2(v0, o0, lo);
                    smw[V_OFF + rp0 * 264 + c]        = hi;
                    smw[V_OFF + 8448 + rp0 * 264 + c] = lo;
                    hi = pack2(v1, o1, lo);
                    smw[V_OFF + rp0 * 264 + c + 1]        = hi;
                    smw[V_OFF + 8448 + rp0 * 264 + c + 1] = lo;
                    hi = pack2(v2, o2, lo);
                    smw[V_OFF + rp1 * 264 + c]        = hi;
                    smw[V_OFF + 8448 + rp1 * 264 + c] = lo;
                    hi = pack2(v3, o3, lo);
                    smw[V_OFF + rp1 * 264 + c + 1]        = hi;
                    smw[V_OFF + 8448 + rp1 * 264 + c + 1] = lo;
                }
            }
        }
    }
    __syncthreads();

    // ---- attention: warp w -> q rows (w>>1)*16.., heads (w&1)*4.. ----
    const int qb = w >> 1;
    const int q0 = qb * 16 + g;
    const int h0 = (w & 1) * 4;
    uint32_t* ph = smw + w * 1152;       // P hi [16][36]
    uint32_t* pl = ph + 576;             // P lo [16][36]

    for (int hh = 0; hh < 4; hh++) {
        const int h = h0 + hh;

        // S = Q K^T + bias
        float sacc[8][4];
        {
            const float* bb = g_bias + h * 4096;
            int r0m = (q0 & 63) * 64, r1m = ((q0 + 8) & 63) * 64;
            #pragma unroll
            for (int j = 0; j < 8; j++) {
                int key = 8 * j + 2 * t;
                sacc[j][0] = __ldg(bb + r0m + key);
                sacc[j][1] = __ldg(bb + r0m + key + 1);
                sacc[j][2] = __ldg(bb + r1m + key);
                sacc[j][3] = __ldg(bb + r1m + key + 1);
            }
        }
        #pragma unroll
        for (int ks = 0; ks < 2; ks++) {
            const uint32_t* qhp = g_qh + h * 2048;
            const uint32_t* qlp = g_ql + h * 2048;
            int wbase = 8 * ks + t;
            uint32_t ah[4], al[4];
            ah[0] = __ldg(qhp + q0 * 16 + wbase);
            ah[1] = __ldg(qhp + (q0 + 8) * 16 + wbase);
            ah[2] = __ldg(qhp + q0 * 16 + wbase + 4);
            ah[3] = __ldg(qhp + (q0 + 8) * 16 + wbase + 4);
            al[0] = __ldg(qlp + q0 * 16 + wbase);
            al[1] = __ldg(qlp + (q0 + 8) * 16 + wbase);
            al[2] = __ldg(qlp + q0 * 16 + wbase + 4);
            al[3] = __ldg(qlp + (q0 + 8) * 16 + wbase + 4);
            #pragma unroll
            for (int j = 0; j < 8; j++) {
                int n = 8 * j + g;
                int kb = K_OFF + n * 132 + h * 16 + 8 * ks + t;
                uint32_t bh[2] = { smw[kb], smw[kb + 4] };
                uint32_t bl[2] = { smw[kb + 8448], smw[kb + 8448 + 4] };
                mma3(sacc[j], ah, al, bh, bl);
            }
        }

        // softmax over 64 keys (rows live in 4-lane groups)
        float m0 = -1e30f, m1 = -1e30f;
        #pragma unroll
        for (int j = 0; j < 8; j++) {
            m0 = fmaxf(m0, fmaxf(sacc[j][0], sacc[j][1]));
            m1 = fmaxf(m1, fmaxf(sacc[j][2], sacc[j][3]));
        }
        m0 = fmaxf(m0, __shfl_xor_sync(0xffffffffu, m0, 1));
        m0 = fmaxf(m0, __shfl_xor_sync(0xffffffffu, m0, 2));
        m1 = fmaxf(m1, __shfl_xor_sync(0xffffffffu, m1, 1));
        m1 = fmaxf(m1, __shfl_xor_sync(0xffffffffu, m1, 2));
        float s0 = 0.f, s1 = 0.f;
        #pragma unroll
        for (int j = 0; j < 8; j++) {
            sacc[j][0] = __expf(sacc[j][0] - m0); s0 += sacc[j][0];
            sacc[j][1] = __expf(sacc[j][1] - m0); s0 += sacc[j][1];
            sacc[j][2] = __expf(sacc[j][2] - m1); s1 += sacc[j][2];
            sacc[j][3] = __expf(sacc[j][3] - m1); s1 += sacc[j][3];
        }
        s0 += __shfl_xor_sync(0xffffffffu, s0, 1);
        s0 += __shfl_xor_sync(0xffffffffu, s0, 2);
        s1 += __shfl_xor_sync(0xffffffffu, s1, 1);
        s1 += __shfl_xor_sync(0xffffffffu, s1, 2);
        float inv0 = 1.0f / s0, inv1 = 1.0f / s1;

        // pack P (token-pair words)
        #pragma unroll
        for (int j = 0; j < 8; j++) {
            int wd = 4 * j + t;
            uint32_t lo, hi;
            hi = pack2(sacc[j][0] * inv0, sacc[j][1] * inv0, lo);
            ph[g * 36 + wd] = hi; pl[g * 36 + wd] = lo;
            hi = pack2(sacc[j][2] * inv1, sacc[j][3] * inv1, lo);
            ph[(g + 8) * 36 + wd] = hi; pl[(g + 8) * 36 + wd] = lo;
        }
        __syncwarp();

        // O = P @ V   (M=16, N=32, K=64), bf16x3
        float oacc[4][4];
        #pragma unroll
        for (int j = 0; j < 4; j++)
            #pragma unroll
            for (int e = 0; e < 4; e++) oacc[j][e] = 0.f;

        #pragma unroll
        for (int ks = 0; ks < 4; ks++) {
            uint32_t ah[4], al[4];
            int pw0 = 8 * ks + t;
            ah[0] = ph[g * 36 + pw0];       ah[1] = ph[(g + 8) * 36 + pw0];
            ah[2] = ph[g * 36 + pw0 + 4];   ah[3] = ph[(g + 8) * 36 + pw0 + 4];
            al[0] = pl[g * 36 + pw0];       al[1] = pl[(g + 8) * 36 + pw0];
            al[2] = pl[g * 36 + pw0 + 4];   al[3] = pl[(g + 8) * 36 + pw0 + 4];
            #pragma unroll
            for (int j = 0; j < 4; j++) {
                int d = h * 32 + 8 * j + g;
                int vb = V_OFF + (8 * ks + t) * 264 + d;
                uint32_t bh[2] = { smw[vb], smw[vb + 4 * 264] };
                uint32_t bl[2] = { smw[vb + 8448], smw[vb + 8448 + 4 * 264] };
                mma3(oacc[j], ah, al, bh, bl);
            }
        }

        // write O packed to gmem
        size_t rbase = (size_t)bw * 128;
        #pragma unroll
        for (int j = 0; j < 4; j++) {
            int wc2 = h * 16 + 4 * j + t;
            uint32_t lo, hi;
            hi = pack2(oacc[j][0], oacc[j][1], lo);
            g_outh[(rbase + q0) * 128 + wc2] = hi;
            g_outl[(rbase + q0) * 128 + wc2] = lo;
            hi = pack2(oacc[j][2], oacc[j][3], lo);
            g_outh[(rbase + q0 + 8) * 128 + wc2] = hi;
            g_outl[(rbase + q0 + 8) * 128 + wc2] = lo;
        }
        __syncwarp();
    }
}

// ---------------- projection GEMM: out = outpre @ proj_w^T + proj_b ----------
// smem words: Ash[8][136]=1088 @0, Asl @1096, Bsh @2192, Bsl @3288; total 4376
__global__ __launch_bounds__(256)
void proj_kernel(const float* __restrict__ pb, float* __restrict__ out) {
    __shared__ uint32_t sm[4376];
    const int tid = threadIdx.x;
    const int w = tid >> 5, lane = tid & 31, g = lane >> 2, t = lane & 3;
    const size_t m0 = (size_t)(blockIdx.x >> 1) * 128;
    const int n0 = (blockIdx.x & 1) * 128;
    const int wm = (w >> 1) * 32, wn = (w & 1) * 64;

    float acc[2][8][4];
    #pragma unroll
    for (int mt = 0; mt < 2; mt++)
        #pragma unroll
        for (int j = 0; j < 8; j++)
            #pragma unroll
            for (int e = 0; e < 4; e++) acc[mt][j][e] = 0.f;

    for (int kc = 0; kc < 16; kc++) {
        __syncthreads();
        {
            int r = tid >> 1, half = tid & 1;
            const uint32_t* sa = (half ? g_outl : g_outh) + (m0 + r) * 128 + kc * 8;
            uint32_t* da = sm + (half ? 1096 : 0);
            uint4 a4 = *(const uint4*)sa; uint4 b4 = *(const uint4*)(sa + 4);
            da[0 * 136 + r] = a4.x; da[1 * 136 + r] = a4.y;
            da[2 * 136 + r] = a4.z; da[3 * 136 + r] = a4.w;
            da[4 * 136 + r] = b4.x; da[5 * 136 + r] = b4.y;
            da[6 * 136 + r] = b4.z; da[7 * 136 + r] = b4.w;
            const uint32_t* sb = (half ? g_pwl : g_pwh) + (size_t)(n0 + r) * 128 + kc * 8;
            uint32_t* db = sm + (half ? 3288 : 2192);
            uint4 c4 = *(const uint4*)sb; uint4 d4 = *(const uint4*)(sb + 4);
            db[0 * 136 + r] = c4.x; db[1 * 136 + r] = c4.y;
            db[2 * 136 + r] = c4.z; db[3 * 136 + r] = c4.w;
            db[4 * 136 + r] = d4.x; db[5 * 136 + r] = d4.y;
            db[6 * 136 + r] = d4.z; db[7 * 136 + r] = d4.w;
        }
        __syncthreads();

        uint32_t ah[2][4], al[2][4];
        #pragma unroll
        for (int mt = 0; mt < 2; mt++) {
            int r = wm + mt * 16 + g;
            ah[mt][0] = sm[t * 136 + r];            ah[mt][1] = sm[t * 136 + r + 8];
            ah[mt][2] = sm[(t + 4) * 136 + r];      ah[mt][3] = sm[(t + 4) * 136 + r + 8];
            al[mt][0] = sm[1096 + t * 136 + r];     al[mt][1] = sm[1096 + t * 136 + r + 8];
            al[mt][2] = sm[1096 + (t + 4) * 136 + r]; al[mt][3] = sm[1096 + (t + 4) * 136 + r + 8];
        }
        #pragma unroll
        for (int j = 0; j < 8; j++) {
            int n = wn + 8 * j + g;
            uint32_t bh[2] = { sm[2192 + t * 136 + n], sm[2192 + (t + 4) * 136 + n] };
            uint32_t bl[2] = { sm[3288 + t * 136 + n], sm[3288 + (t + 4) * 136 + n] };
            mma3(acc[0][j], ah[0], al[0], bh, bl);
            mma3(acc[1][j], ah[1], al[1], bh, bl);
        }
    }

    #pragma unroll
    for (int mt = 0; mt < 2; mt++)
        #pragma unroll
        for (int j = 0; j < 8; j++) {
            int oc = n0 + wn + 8 * j + 2 * t;
            float b0 = __ldg(pb + oc), b1 = __ldg(pb + oc + 1);
            size_t r = m0 + wm + mt * 16 + g;
            *(float2*)(out + r * 256 + oc) =
                make_float2(acc[mt][j][0] + b0, acc[mt][j][1] + b1);
            *(float2*)(out + (r + 8) * 256 + oc) =
                make_float2(acc[mt][j][2] + b0, acc[mt][j][3] + b1);
        }
}

// ---------------- launch ----------------
static const float* find_by_size(void* const* d_in, const int* in_sizes,
                                 int n_in, int want) {
    for (int i = 0; i < n_in; i++)
        if (in_sizes[i] == want) return (const float*)d_in[i];
    return nullptr;
}

extern "C" void kernel_launch(void* const* d_in, const int* in_sizes, int n_in,
                              void* d_out, int out_size) {
    const float* embeds = find_by_size(d_in, in_sizes, n_in, 128 * 256);
    const float* x      = find_by_size(d_in, in_sizes, n_in, 2 * 256 * 256 * 256);
    const float* rpb    = find_by_size(d_in, in_sizes, n_in, 225 * 8);
    const float* kvw    = find_by_size(d_in, in_sizes, n_in, 512 * 256);
    const float* kvb    = find_by_size(d_in, in_sizes, n_in, 512);
    const float* pw     = find_by_size(d_in, in_sizes, n_in, 256 * 256);
    const float* pb     = find_by_size(d_in, in_sizes, n_in, 256);
    float* out = (float*)d_out;

    prep_q<<<(HEADS * N1 * 16 + 255) / 256, 256>>>(embeds);
    prep_bias<<<(HEADS * WIN * WIN + 255) / 256, 256>>>(rpb);
    prep_w<<<(512 * 128 + 256 * 128 + 255) / 256, 256>>>(kvw, pw);

    cudaFuncSetAttribute(win_attn,
                         cudaFuncAttributeMaxDynamicSharedMemorySize, 221696);
    win_attn<<<NWIN, 512, 221696>>>(x, kvb);

    proj_kernel<<<NWIN * 2, 256>>>(pb, out);
}

// round 7
// speedup vs baseline: 5.6578x; 1.6296x over previous
#include <cuda_runtime.h>
#include <cuda_bf16.h>
#include <math.h>
#include <stdint.h>

#define DIM 256
#define HEADS 8
#define WIN 64
#define N1 128
#define NWIN 2048
#define SCALE 0.17677669529663687f

// ---------------- device scratch (fragment-packed) ----------------
__device__ uint4 g_q4h[8 * 8 * 2 * 32];          // [h][qb][ks][lane]
__device__ uint4 g_q4l[8 * 8 * 2 * 32];
__device__ float4 g_b4[8 * 8 * 8 * 32];          // [h][qb][j][lane]
__device__ uint4 g_kvw4[8 * 2 * 4 * 512];        // [chunk][sub][t][n]
__device__ uint4 g_pw4[16 * 4 * 256];            // [kc][t][n]
__device__ uint4 g_outh4[(size_t)NWIN * 8 * 16 * 32];  // [bw][qb][kc][t*8+g]
__device__ uint4 g_outl4[(size_t)NWIN * 8 * 16 * 32];

// ---------------- helpers ----------------
__device__ __forceinline__ uint32_t pack2(float x0, float x1, uint32_t& lo) {
    __nv_bfloat16 h0 = __float2bfloat16(x0);
    __nv_bfloat16 h1 = __float2bfloat16(x1);
    __nv_bfloat16 l0 = __float2bfloat16(x0 - __bfloat162float(h0));
    __nv_bfloat16 l1 = __float2bfloat16(x1 - __bfloat162float(h1));
    lo = ((uint32_t)__bfloat16_as_ushort(l1) << 16) | (uint32_t)__bfloat16_as_ushort(l0);
    return ((uint32_t)__bfloat16_as_ushort(h1) << 16) | (uint32_t)__bfloat16_as_ushort(h0);
}

__device__ __forceinline__ void mma16(float c[4], uint32_t a0, uint32_t a1,
                                      uint32_t a2, uint32_t a3,
                                      uint32_t b0, uint32_t b1) {
    asm volatile(
        "mma.sync.aligned.m16n8k16.row.col.f32.bf16.bf16.f32 "
        "{%0,%1,%2,%3},{%4,%5,%6,%7},{%8,%9},{%0,%1,%2,%3};\n"
        : "+f"(c[0]), "+f"(c[1]), "+f"(c[2]), "+f"(c[3])
        : "r"(a0), "r"(a1), "r"(a2), "r"(a3), "r"(b0), "r"(b1));
}
__device__ __forceinline__ void mma3(float c[4], const uint4& ah, const uint4& al,
                                     const uint4& B) {
    mma16(c, ah.x, ah.y, ah.z, ah.w, B.x, B.y);
    mma16(c, ah.x, ah.y, ah.z, ah.w, B.z, B.w);
    mma16(c, al.x, al.y, al.z, al.w, B.x, B.y);
}

// bias formula (relative position)
__device__ __forceinline__ float bias_val(const float* rpb, int h, int r, int k) {
    int i1 = r >> 3, j1 = r & 7, i2 = k >> 3, j2 = k & 7;
    int idx = (i1 - i2 + 7) * 15 + (j1 - j2 + 7);
    return rpb[idx * HEADS + h];
}

// ---------------- prep kernels ----------------
__global__ void prep_q4(const float* __restrict__ e) {
    int i = blockIdx.x * blockDim.x + threadIdx.x;
    if (i >= 4096) return;
    int lane = i & 31, ks = (i >> 5) & 1, qb = (i >> 6) & 7, h = i >> 9;
    int g = lane >> 2, t = lane & 3;
    int q0 = qb * 16 + g;
    uint4 hi, lo;
    int d0 = h * 32 + (8 * ks + t) * 2;
    int d1 = h * 32 + (8 * ks + t + 4) * 2;
    hi.x = pack2(e[q0 * DIM + d0] * SCALE, e[q0 * DIM + d0 + 1] * SCALE, lo.x);
    hi.y = pack2(e[(q0 + 8) * DIM + d0] * SCALE, e[(q0 + 8) * DIM + d0 + 1] * SCALE, lo.y);
    hi.z = pack2(e[q0 * DIM + d1] * SCALE, e[q0 * DIM + d1 + 1] * SCALE, lo.z);
    hi.w = pack2(e[(q0 + 8) * DIM + d1] * SCALE, e[(q0 + 8) * DIM + d1 + 1] * SCALE, lo.w);
    g_q4h[i] = hi; g_q4l[i] = lo;
}

__global__ void prep_b4(const float* __restrict__ rpb) {
    int i = blockIdx.x * blockDim.x + threadIdx.x;
    if (i >= 16384) return;
    int lane = i & 31, j = (i >> 5) & 7, qb = (i >> 8) & 7, h = i >> 11;
    int g = lane >> 2, t = lane & 3;
    int r0 = (qb * 16 + g) & 63, r1 = (qb * 16 + g + 8) & 63;
    int c = 8 * j + 2 * t;
    float4 v;
    v.x = bias_val(rpb, h, r0, c);
    v.y = bias_val(rpb, h, r0, c + 1);
    v.z = bias_val(rpb, h, r1, c);
    v.w = bias_val(rpb, h, r1, c + 1);
    g_b4[i] = v;
}

// FIXED: kvw needs 32768 fragment slots (chunk 0..7), pw needs 16384.
__global__ void prep_w4(const float* __restrict__ kvw, const float* __restrict__ pw) {
    int i = blockIdx.x * blockDim.x + threadIdx.x;
    if (i < 32768) {
        int n = i & 511, t = (i >> 9) & 3, sub = (i >> 11) & 1, chunk = i >> 12; // 0..7
        int kwA = chunk * 16 + sub * 8 + t, kwB = kwA + 4;
        uint4 v;
        v.x = pack2(kvw[n * 256 + 2 * kwA], kvw[n * 256 + 2 * kwA + 1], v.z);
        v.y = pack2(kvw[n * 256 + 2 * kwB], kvw[n * 256 + 2 * kwB + 1], v.w);
        g_kvw4[i] = v;
    } else if (i < 49152) {
        int ii = i - 32768;
        int n = ii & 255, t = (ii >> 8) & 3, kc = ii >> 10;  // 0..15
        int kwA = kc * 8 + t, kwB = kwA + 4;
        uint4 v;
        v.x = pack2(pw[n * 256 + 2 * kwA], pw[n * 256 + 2 * kwA + 1], v.z);
        v.y = pack2(pw[n * 256 + 2 * kwB], pw[n * 256 + 2 * kwB + 1], v.w);
        g_pw4[ii] = v;
    }
}

// ---------------- fused window kernel ----------------
// smem (uint4 units):
//  a4  @ 0      size 4352  (hi plane 2176 [kcg*136 + t*34 + m*8 + g], lo +2176)
//                also aliased by v4 [ks*1024 + d*4 + tq] (4096) in attn phase
//  k4  @ 4352   size 4352  [key*68 + G*4 + t]
//  ws4 @ 8704   size 4112  [sub*2056 + t*514 + n]
//  kvb @ uint4 12816 (512 floats)
// total 12944 uint4 = 207104 bytes
#define A4_OFF  0
#define K4_OFF  4352
#define WS4_OFF 8704
#define SMEM_BYTES 207104

extern __shared__ uint4 sm4[];

__global__ __launch_bounds__(512, 1)
void win_attn(const float* __restrict__ x, const float* __restrict__ kvb) {
    const int tid  = threadIdx.x;
    const int bw   = blockIdx.x;
    const int b    = bw >> 10;
    const int wr   = (bw >> 5) & 31;
    const int wc   = bw & 31;
    const int w    = tid >> 5;
    const int lane = tid & 31;
    const int g    = lane >> 2;
    const int t    = lane & 3;
    float* kvbf = (float*)(sm4 + 12816);
    uint32_t* a4w = (uint32_t*)sm4;

    // ---- load window tile, split+pack, scatter into a4 fragment layout ----
    {
        const float4* xv = (const float4*)(x +
            ((size_t)((b * 256 + wr * 8) * 256 + wc * 8)) * 256);
        #pragma unroll
        for (int i = 0; i < 8; i++) {
            int idx = tid + i * 512;
            int tok = idx >> 6, c4 = idx & 63;
            int r = tok >> 3, cc = tok & 7;
            float4 v = xv[r * 16384 + cc * 64 + c4];
            int m = tok >> 4, gg = tok & 15;
            int g2 = gg & 7, r8 = gg >> 3;
            int kcg = c4 >> 2, rem = c4 & 3;
            uint32_t lo0, lo1;
            uint32_t hi0 = pack2(v.x, v.y, lo0);
            uint32_t hi1 = pack2(v.z, v.w, lo1);
            int tt0 = 2 * rem, tt1 = tt0 + 1;
            int i0 = kcg * 136 + (tt0 & 3) * 34 + m * 8 + g2;
            int w0 = r8 + 2 * (tt0 >> 2);
            a4w[i0 * 4 + w0] = hi0;
            a4w[(i0 + 2176) * 4 + w0] = lo0;
            int i1 = kcg * 136 + (tt1 & 3) * 34 + m * 8 + g2;
            int w1 = r8 + 2 * (tt1 >> 2);
            a4w[i1 * 4 + w1] = hi1;
            a4w[(i1 + 2176) * 4 + w1] = lo1;
        }
        kvbf[tid] = kvb[tid];
    }

    // ---- KV GEMM: single pass over 512 cols; 16 warps = 2m x 8n ----
    const int wmK = (w >> 3) * 32;
    const int wnK = (w & 7) * 64;
    const int mB  = (w >> 3) * 2;

    float acc[2][8][4];
    #pragma unroll
    for (int mt = 0; mt < 2; mt++)
        #pragma unroll
        for (int j = 0; j < 8; j++)
            #pragma unroll
            for (int e = 0; e < 4; e++) acc[mt][j][e] = 0.f;

    for (int chunk = 0; chunk < 8; chunk++) {
        __syncthreads();
        #pragma unroll
        for (int k = 0; k < 8; k++) {
            int gi = tid + k * 512;
            int n = gi & 511, tt = (gi >> 9) & 3, sub = gi >> 11;
            sm4[WS4_OFF + sub * 2056 + tt * 514 + n] = g_kvw4[chunk * 4096 + gi];
        }
        __syncthreads();
        #pragma unroll
        for (int sub = 0; sub < 2; sub++) {
            int kcg = chunk * 2 + sub;
            uint4 Ah[2], Al[2];
            #pragma unroll
            for (int mt = 0; mt < 2; mt++) {
                int ai = A4_OFF + kcg * 136 + t * 34 + (mB + mt) * 8 + g;
                Ah[mt] = sm4[ai];
                Al[mt] = sm4[ai + 2176];
            }
            #pragma unroll
            for (int j = 0; j < 8; j++) {
                uint4 B = sm4[WS4_OFF + sub * 2056 + t * 514 + wnK + 8 * j + g];
                mma3(acc[0][j], Ah[0], Al[0], B);
                mma3(acc[1][j], Ah[1], Al[1], B);
            }
        }
    }
    __syncthreads();   // all a4 reads done (v4 will alias a4)

    // ---- epilogues: K warps (wnK<256) -> k4 ; V warps -> v4 (alias a4) ----
    if (wnK < 256) {
        #pragma unroll
        for (int mt = 0; mt < 2; mt++) {
            int key0 = wmK + mt * 16 + g;
            #pragma unroll
            for (int jp = 0; jp < 4; jp++) {
                int j = 2 * jp;
                int c  = wnK + 8 * j + 2 * t;
                int c2 = c + 8;
                float b0 = kvbf[c], b1 = kvbf[c + 1];
                float b2 = kvbf[c2], b3 = kvbf[c2 + 1];
                int G = (wnK >> 4) + jp;
                uint4 u;
                u.x = pack2(acc[mt][j][0] + b0, acc[mt][j][1] + b1, u.z);
                u.y = pack2(acc[mt][j + 1][0] + b2, acc[mt][j + 1][1] + b3, u.w);
                sm4[K4_OFF + key0 * 68 + G * 4 + t] = u;
                uint4 v;
                v.x = pack2(acc[mt][j][2] + b0, acc[mt][j][3] + b1, v.z);
                v.y = pack2(acc[mt][j + 1][2] + b2, acc[mt][j + 1][3] + b3, v.w);
                sm4[K4_OFF + (key0 + 8) * 68 + G * 4 + t] = v;
            }
        }
    } else {
        #pragma unroll
        for (int mt = 0; mt < 2; mt++) {
            int ks = mB + mt;
            #pragma unroll
            for (int j = 0; j < 8; j++) {
                int c = wnK - 256 + 8 * j + 2 * t;
                float b0 = kvbf[256 + c], b1 = kvbf[256 + c + 1];
                float v0 = acc[mt][j][0] + b0, v1 = acc[mt][j][1] + b1;
                float v2 = acc[mt][j][2] + b0, v3 = acc[mt][j][3] + b1;
                float o0 = __shfl_xor_sync(0xffffffffu, v0, 4);
                float o1 = __shfl_xor_sync(0xffffffffu, v1, 4);
                float o2 = __shfl_xor_sync(0xffffffffu, v2, 4);
                float o3 = __shfl_xor_sync(0xffffffffu, v3, 4);
                if ((g & 1) == 0) {
                    int tq = g >> 1;
                    uint4 u;
                    u.x = pack2(v0, o0, u.z);
                    u.y = pack2(v2, o2, u.w);
                    sm4[A4_OFF + ks * 1024 + c * 4 + tq] = u;
                    uint4 v;
                    v.x = pack2(v1, o1, v.z);
                    v.y = pack2(v3, o3, v.w);
                    sm4[A4_OFF + ks * 1024 + (c + 1) * 4 + tq] = v;
                }
            }
        }
    }
    __syncthreads();

    // ---- attention: 16 warps = 8 q-blocks x 2 head-groups ----
    const int qb = w >> 1;
    const int hbase = (w & 1) * 4;

    for (int hh = 0; hh < 4; hh++) {
        const int h = hbase + hh;

        // S = bias; += Q K^T
        float sacc[8][4];
        #pragma unroll
        for (int j = 0; j < 8; j++) {
            float4 bv = __ldg(&g_b4[((h * 8 + qb) * 8 + j) * 32 + lane]);
            sacc[j][0] = bv.x; sacc[j][1] = bv.y;
            sacc[j][2] = bv.z; sacc[j][3] = bv.w;
        }
        #pragma unroll
        for (int ks = 0; ks < 2; ks++) {
            uint4 Qh = __ldg(&g_q4h[((h * 8 + qb) * 2 + ks) * 32 + lane]);
            uint4 Ql = __ldg(&g_q4l[((h * 8 + qb) * 2 + ks) * 32 + lane]);
            #pragma unroll
            for (int j = 0; j < 8; j++) {
                uint4 K = sm4[K4_OFF + (8 * j + g) * 68 + (h * 2 + ks) * 4 + t];
                mma3(sacc[j], Qh, Ql, K);
            }
        }

        // softmax over 64 keys (rows in 4-lane groups)
        float m0 = -1e30f, m1 = -1e30f;
        #pragma unroll
        for (int j = 0; j < 8; j++) {
            m0 = fmaxf(m0, fmaxf(sacc[j][0], sacc[j][1]));
            m1 = fmaxf(m1, fmaxf(sacc[j][2], sacc[j][3]));
        }
        m0 = fmaxf(m0, __shfl_xor_sync(0xffffffffu, m0, 1));
        m0 = fmaxf(m0, __shfl_xor_sync(0xffffffffu, m0, 2));
        m1 = fmaxf(m1, __shfl_xor_sync(0xffffffffu, m1, 1));
        m1 = fmaxf(m1, __shfl_xor_sync(0xffffffffu, m1, 2));
        float s0 = 0.f, s1 = 0.f;
        #pragma unroll
        for (int j = 0; j < 8; j++) {
            sacc[j][0] = __expf(sacc[j][0] - m0); s0 += sacc[j][0];
            sacc[j][1] = __expf(sacc[j][1] - m0); s0 += sacc[j][1];
            sacc[j][2] = __expf(sacc[j][2] - m1); s1 += sacc[j][2];
            sacc[j][3] = __expf(sacc[j][3] - m1); s1 += sacc[j][3];
        }
        s0 += __shfl_xor_sync(0xffffffffu, s0, 1);
        s0 += __shfl_xor_sync(0xffffffffu, s0, 2);
        s1 += __shfl_xor_sync(0xffffffffu, s1, 1);
        s1 += __shfl_xor_sync(0xffffffffu, s1, 2);
        float inv0 = 1.0f / s0, inv1 = 1.0f / s1;
        #pragma unroll
        for (int j = 0; j < 8; j++) {
            sacc[j][0] *= inv0; sacc[j][1] *= inv0;
            sacc[j][2] *= inv1; sacc[j][3] *= inv1;
        }

        // O = P V : A-fragments repacked from sacc IN REGISTERS
        float oacc[4][4];
        #pragma unroll
        for (int j = 0; j < 4; j++)
            #pragma unroll
            for (int e = 0; e < 4; e++) oacc[j][e] = 0.f;

        #pragma unroll
        for (int ks = 0; ks < 4; ks++) {
            uint4 ah, al;
            ah.x = pack2(sacc[2 * ks][0], sacc[2 * ks][1], al.x);
            ah.y = pack2(sacc[2 * ks][2], sacc[2 * ks][3], al.y);
            ah.z = pack2(sacc[2 * ks + 1][0], sacc[2 * ks + 1][1], al.z);
            ah.w = pack2(sacc[2 * ks + 1][2], sacc[2 * ks + 1][3], al.w);
            #pragma unroll
            for (int j = 0; j < 4; j++) {
                uint4 V = sm4[A4_OFF + ks * 1024 + (h * 32 + 8 * j + g) * 4 + t];
                mma3(oacc[j], ah, al, V);
            }
        }

        // write O in proj's A-fragment layout
        #pragma unroll
        for (int jp = 0; jp < 2; jp++) {
            int j = 2 * jp;
            int kco = h * 2 + jp;
            uint4 hi, lo;
            hi.x = pack2(oacc[j][0], oacc[j][1], lo.x);
            hi.y = pack2(oacc[j][2], oacc[j][3], lo.y);
            hi.z = pack2(oacc[j + 1][0], oacc[j + 1][1], lo.z);
            hi.w = pack2(oacc[j + 1][2], oacc[j + 1][3], lo.w);
            size_t oidx = (((size_t)bw * 8 + qb) * 16 + kco) * 32 + t * 8 + g;
            g_outh4[oidx] = hi;
            g_outl4[oidx] = lo;
        }
    }
}

// ---------------- projection GEMM ----------------
__global__ __launch_bounds__(512)
void proj_kernel(const float* __restrict__ pb, float* __restrict__ out) {
    __shared__ uint4 As[520];    // [t*130 + qb*16 + plane*8 + g]
    __shared__ uint4 Bs[1096];   // [t*274 + n]
    const int tid = threadIdx.x;
    const int w = tid >> 5, lane = tid & 31, g = lane >> 2, t = lane & 3;
    const int bw = blockIdx.x;
    const int wm = (w >> 2) * 32, wn = (w & 3) * 64;
    const int qB = (w >> 2) * 2;

    float acc[2][8][4];
    #pragma unroll
    for (int mt = 0; mt < 2; mt++)
        #pragma unroll
        for (int j = 0; j < 8; j++)
            #pragma unroll
            for (int e = 0; e < 4; e++) acc[mt][j][e] = 0.f;

    for (int kc = 0; kc < 16; kc++) {
        __syncthreads();
        {   // stage A fragments (512 uint4)
            int g2 = tid & 7, plane = (tid >> 3) & 1, qb = (tid >> 4) & 7, tp = tid >> 7;
            const uint4* src = plane ? g_outl4 : g_outh4;
            As[tp * 130 + qb * 16 + plane * 8 + g2] =
                src[(((size_t)bw * 8 + qb) * 16 + kc) * 32 + tp * 8 + g2];
        }
        {   // stage B fragments (1024 uint4)
            #pragma unroll
            for (int k = 0; k < 2; k++) {
                int gi = tid + k * 512;
                int n = gi & 255, tt = gi >> 8;
                Bs[tt * 274 + n] = g_pw4[kc * 1024 + gi];
            }
        }
        __syncthreads();

        uint4 Ah[2], Al[2];
        #pragma unroll
        for (int mt = 0; mt < 2; mt++) {
            int qb = qB + mt;
            Ah[mt] = As[t * 130 + qb * 16 + g];
            Al[mt] = As[t * 130 + qb * 16 + 8 + g];
        }
        #pragma unroll
        for (int j = 0; j < 8; j++) {
            uint4 B = Bs[t * 274 + wn + 8 * j + g];
            mma3(acc[0][j], Ah[0], Al[0], B);
            mma3(acc[1][j], Ah[1], Al[1], B);
        }
    }

    #pragma unroll
    for (int j = 0; j < 8; j++) {
        int oc = wn + 8 * j + 2 * t;
        float b0 = __ldg(pb + oc), b1 = __ldg(pb + oc + 1);
        #pragma unroll
        for (int mt = 0; mt < 2; mt++) {
            size_t r = (size_t)bw * 128 + wm + mt * 16 + g;
            *(float2*)(out + r * 256 + oc) =
                make_float2(acc[mt][j][0] + b0, acc[mt][j][1] + b1);
            *(float2*)(out + (r + 8) * 256 + oc) =
                make_float2(acc[mt][j][2] + b0, acc[mt][j][3] + b1);
        }
    }
}

// ---------------- launch ----------------
static const float* find_by_size(void* const* d_in, const int* in_sizes,
                                 int n_in, int want) {
    for (int i = 0; i < n_in; i++)
        if (in_sizes[i] == want) return (const float*)d_in[i];
    return nullptr;
}

extern "C" void kernel_launch(void* const* d_in, const int* in_sizes, int n_in,
                              void* d_out, int out_size) {
    const float* embeds = find_by_size(d_in, in_sizes, n_in, 128 * 256);
    const float* x      = find_by_size(d_in, in_sizes, n_in, 2 * 256 * 256 * 256);
    const float* rpb    = find_by_size(d_in, in_sizes, n_in, 225 * 8);
    const float* kvw    = find_by_size(d_in, in_sizes, n_in, 512 * 256);
    const float* kvb    = find_by_size(d_in, in_sizes, n_in, 512);
    const float* pw     = find_by_size(d_in, in_sizes, n_in, 256 * 256);
    const float* pb     = find_by_size(d_in, in_sizes, n_in, 256);
    float* out = (float*)d_out;

    prep_q4<<<16, 256>>>(embeds);
    prep_b4<<<64, 256>>>(rpb);
    prep_w4<<<192, 256>>>(kvw, pw);   // 49152 threads: 32768 kvw + 16384 pw

    cudaFuncSetAttribute(win_attn,
                         cudaFuncAttributeMaxDynamicSharedMemorySize, SMEM_BYTES);
    win_attn<<<NWIN, 512, SMEM_BYTES>>>(x, kvb);

    proj_kernel<<<NWIN, 512>>>(pb, out);
}

// round 8
// speedup vs baseline: 7.0467x; 1.2455x over previous
#include <cuda_runtime.h>
#include <cuda_bf16.h>
#include <math.h>
#include <stdint.h>

#define DIM 256
#define HEADS 8
#define WIN 64
#define N1 128
#define NWIN 2048
#define SCALE 0.17677669529663687f

// ---------------- device scratch (fragment-packed) ----------------
__device__ uint4 g_q4h[8 * 8 * 2 * 32];          // [h][qb][ks][lane]
__device__ uint4 g_q4l[8 * 8 * 2 * 32];
__device__ float4 g_b4[8 * 8 * 8 * 32];          // [h][qb][j][lane]
__device__ uint4 g_kvw4[16 * 4 * 512];           // [kcg][t][n]
__device__ uint4 g_pw4[16 * 4 * 256];            // [kc][t][n]

// ---------------- helpers ----------------
__device__ __forceinline__ uint32_t pack2(float x0, float x1, uint32_t& lo) {
    __nv_bfloat16 h0 = __float2bfloat16(x0);
    __nv_bfloat16 h1 = __float2bfloat16(x1);
    __nv_bfloat16 l0 = __float2bfloat16(x0 - __bfloat162float(h0));
    __nv_bfloat16 l1 = __float2bfloat16(x1 - __bfloat162float(h1));
    lo = ((uint32_t)__bfloat16_as_ushort(l1) << 16) | (uint32_t)__bfloat16_as_ushort(l0);
    return ((uint32_t)__bfloat16_as_ushort(h1) << 16) | (uint32_t)__bfloat16_as_ushort(h0);
}

__device__ __forceinline__ void mma16(float c[4], uint32_t a0, uint32_t a1,
                                      uint32_t a2, uint32_t a3,
                                      uint32_t b0, uint32_t b1) {
    asm volatile(
        "mma.sync.aligned.m16n8k16.row.col.f32.bf16.bf16.f32 "
        "{%0,%1,%2,%3},{%4,%5,%6,%7},{%8,%9},{%0,%1,%2,%3};\n"
        : "+f"(c[0]), "+f"(c[1]), "+f"(c[2]), "+f"(c[3])
        : "r"(a0), "r"(a1), "r"(a2), "r"(a3), "r"(b0), "r"(b1));
}
__device__ __forceinline__ void mma3(float c[4], const uint4& ah, const uint4& al,
                                     const uint4& B) {
    mma16(c, ah.x, ah.y, ah.z, ah.w, B.x, B.y);
    mma16(c, ah.x, ah.y, ah.z, ah.w, B.z, B.w);
    mma16(c, al.x, al.y, al.z, al.w, B.x, B.y);
}

__device__ __forceinline__ void cp16(uint32_t dst_smem, const void* src) {
    asm volatile("cp.async.cg.shared.global [%0], [%1], 16;\n"
                 :: "r"(dst_smem), "l"(src));
}
#define CP_COMMIT() asm volatile("cp.async.commit_group;\n")
#define CP_WAIT1()  asm volatile("cp.async.wait_group 1;\n")
#define CP_WAIT0()  asm volatile("cp.async.wait_group 0;\n")

// bias formula (relative position)
__device__ __forceinline__ float bias_val(const float* rpb, int h, int r, int k) {
    int i1 = r >> 3, j1 = r & 7, i2 = k >> 3, j2 = k & 7;
    int idx = (i1 - i2 + 7) * 15 + (j1 - j2 + 7);
    return rpb[idx * HEADS + h];
}

// ---------------- prep kernels ----------------
__global__ void prep_q4(const float* __restrict__ e) {
    int i = blockIdx.x * blockDim.x + threadIdx.x;
    if (i >= 4096) return;
    int lane = i & 31, ks = (i >> 5) & 1, qb = (i >> 6) & 7, h = i >> 9;
    int g = lane >> 2, t = lane & 3;
    int q0 = qb * 16 + g;
    uint4 hi, lo;
    int d0 = h * 32 + (8 * ks + t) * 2;
    int d1 = h * 32 + (8 * ks + t + 4) * 2;
    hi.x = pack2(e[q0 * DIM + d0] * SCALE, e[q0 * DIM + d0 + 1] * SCALE, lo.x);
    hi.y = pack2(e[(q0 + 8) * DIM + d0] * SCALE, e[(q0 + 8) * DIM + d0 + 1] * SCALE, lo.y);
    hi.z = pack2(e[q0 * DIM + d1] * SCALE, e[q0 * DIM + d1 + 1] * SCALE, lo.z);
    hi.w = pack2(e[(q0 + 8) * DIM + d1] * SCALE, e[(q0 + 8) * DIM + d1 + 1] * SCALE, lo.w);
    g_q4h[i] = hi; g_q4l[i] = lo;
}

__global__ void prep_b4(const float* __restrict__ rpb) {
    int i = blockIdx.x * blockDim.x + threadIdx.x;
    if (i >= 16384) return;
    int lane = i & 31, j = (i >> 5) & 7, qb = (i >> 8) & 7, h = i >> 11;
    int g = lane >> 2, t = lane & 3;
    int r0 = (qb * 16 + g) & 63, r1 = (qb * 16 + g + 8) & 63;
    int c = 8 * j + 2 * t;
    float4 v;
    v.x = bias_val(rpb, h, r0, c);
    v.y = bias_val(rpb, h, r0, c + 1);
    v.z = bias_val(rpb, h, r1, c);
    v.w = bias_val(rpb, h, r1, c + 1);
    g_b4[i] = v;
}

__global__ void prep_w4(const float* __restrict__ kvw, const float* __restrict__ pw) {
    int i = blockIdx.x * blockDim.x + threadIdx.x;
    if (i < 32768) {
        int n = i & 511, t = (i >> 9) & 3, kcg = i >> 11;   // 0..15
        int kwA = kcg * 8 + t, kwB = kwA + 4;
        uint4 v;
        v.x = pack2(kvw[n * 256 + 2 * kwA], kvw[n * 256 + 2 * kwA + 1], v.z);
        v.y = pack2(kvw[n * 256 + 2 * kwB], kvw[n * 256 + 2 * kwB + 1], v.w);
        g_kvw4[i] = v;
    } else if (i < 49152) {
        int ii = i - 32768;
        int n = ii & 255, t = (ii >> 8) & 3, kc = ii >> 10;  // 0..15
        int kwA = kc * 8 + t, kwB = kwA + 4;
        uint4 v;
        v.x = pack2(pw[n * 256 + 2 * kwA], pw[n * 256 + 2 * kwA + 1], v.z);
        v.y = pack2(pw[n * 256 + 2 * kwB], pw[n * 256 + 2 * kwB + 1], v.w);
        g_pw4[ii] = v;
    }
}

// ---------------- fused window kernel (KV GEMM + attention + proj) -----------
// smem (uint4 units):
//  a4  @ 0      size 4352  (hi [kcg*136 + t*34 + m*8 + g], lo +2176)
//                phase2: V [ks*1024 + d*4 + tq];  phase3: O/A [kc*520+t*130+qb*16+plane*8+g]
//  k4  @ 4352   size 4352  [key*68 + G*4 + t]     (phase3: part of O/A)
//  ws4 @ 8704   size 4112  KV: ping-pong 2x2056 [buf*2056 + t*514 + n]
//                          proj: ping-pong 2x1096 [buf*1096 + t*274 + n]
//  kvb @ uint4 12816 (512 floats)
// total 12944 uint4 = 207104 bytes
#define A4_OFF  0
#define K4_OFF  4352
#define WS4_OFF 8704
#define SMEM_BYTES 207104

extern __shared__ uint4 sm4[];

__global__ __launch_bounds__(512, 1)
void win_attn(const float* __restrict__ x, const float* __restrict__ kvb,
              const float* __restrict__ pb, float* __restrict__ out) {
    const int tid  = threadIdx.x;
    const int bw   = blockIdx.x;
    const int b    = bw >> 10;
    const int wr   = (bw >> 5) & 31;
    const int wc   = bw & 31;
    const int w    = tid >> 5;
    const int lane = tid & 31;
    const int g    = lane >> 2;
    const int t    = lane & 3;
    float* kvbf = (float*)(sm4 + 12816);
    uint32_t* a4w = (uint32_t*)sm4;
    uint32_t smem_base;
    asm("{ .reg .u64 tmp; cvta.to.shared.u64 tmp, %1; cvt.u32.u64 %0, tmp; }"
        : "=r"(smem_base) : "l"((void*)sm4));

    // ---- prologue: stage kvw kcg0 via cp.async ----
    {
        #pragma unroll
        for (int k = 0; k < 4; k++) {
            int gi = tid + k * 512;
            int n = gi & 511, tt = gi >> 9;
            cp16(smem_base + (WS4_OFF + tt * 514 + n) * 16, &g_kvw4[gi]);
        }
        CP_COMMIT();
    }

    // ---- load window tile, split+pack, scatter into a4 fragment layout ----
    {
        const float4* xv = (const float4*)(x +
            ((size_t)((b * 256 + wr * 8) * 256 + wc * 8)) * 256);
        #pragma unroll
        for (int i = 0; i < 8; i++) {
            int idx = tid + i * 512;
            int tok = idx >> 6, c4 = idx & 63;
            int r = tok >> 3, cc = tok & 7;
            float4 v = xv[r * 16384 + cc * 64 + c4];
            int m = tok >> 4, gg = tok & 15;
            int g2 = gg & 7, r8 = gg >> 3;
            int kcg = c4 >> 2, rem = c4 & 3;
            uint32_t lo0, lo1;
            uint32_t hi0 = pack2(v.x, v.y, lo0);
            uint32_t hi1 = pack2(v.z, v.w, lo1);
            int tt0 = 2 * rem, tt1 = tt0 + 1;
            int i0 = kcg * 136 + (tt0 & 3) * 34 + m * 8 + g2;
            int w0 = r8 + 2 * (tt0 >> 2);
            a4w[i0 * 4 + w0] = hi0;
            a4w[(i0 + 2176) * 4 + w0] = lo0;
            int i1 = kcg * 136 + (tt1 & 3) * 34 + m * 8 + g2;
            int w1 = r8 + 2 * (tt1 >> 2);
            a4w[i1 * 4 + w1] = hi1;
            a4w[(i1 + 2176) * 4 + w1] = lo1;
        }
        kvbf[tid] = kvb[tid];
    }

    // ---- KV GEMM: pipelined over 16 kcg; 16 warps = 2m x 8n ----
    const int wmK = (w >> 3) * 32;
    const int wnK = (w & 7) * 64;
    const int mB  = (w >> 3) * 2;

    float acc[2][8][4];
    #pragma unroll
    for (int mt = 0; mt < 2; mt++)
        #pragma unroll
        for (int j = 0; j < 8; j++)
            #pragma unroll
            for (int e = 0; e < 4; e++) acc[mt][j][e] = 0.f;

    for (int kcg = 0; kcg < 16; kcg++) {
        if (kcg + 1 < 16) {
            int bufn = (kcg + 1) & 1;
            #pragma unroll
            for (int k = 0; k < 4; k++) {
                int gi = tid + k * 512;
                int n = gi & 511, tt = gi >> 9;
                cp16(smem_base + (WS4_OFF + bufn * 2056 + tt * 514 + n) * 16,
                     &g_kvw4[(kcg + 1) * 2048 + gi]);
            }
            CP_COMMIT();
            CP_WAIT1();
        } else {
            CP_WAIT0();
        }
        __syncthreads();

        int bufc = WS4_OFF + (kcg & 1) * 2056;
        uint4 Ah[2], Al[2];
        #pragma unroll
        for (int mt = 0; mt < 2; mt++) {
            int ai = A4_OFF + kcg * 136 + t * 34 + (mB + mt) * 8 + g;
            Ah[mt] = sm4[ai];
            Al[mt] = sm4[ai + 2176];
        }
        #pragma unroll
        for (int j = 0; j < 8; j++) {
            uint4 B = sm4[bufc + t * 514 + wnK + 8 * j + g];
            mma3(acc[0][j], Ah[0], Al[0], B);
            mma3(acc[1][j], Ah[1], Al[1], B);
        }
    }
    __syncthreads();   // all a4 reads done (V will alias a4)

    // ---- epilogues: K warps (wnK<256) -> k4 ; V warps -> a4 alias ----
    if (wnK < 256) {
        #pragma unroll
        for (int mt = 0; mt < 2; mt++) {
            int key0 = wmK + mt * 16 + g;
            #pragma unroll
            for (int jp = 0; jp < 4; jp++) {
                int j = 2 * jp;
                int c  = wnK + 8 * j + 2 * t;
                int c2 = c + 8;
                float b0 = kvbf[c], b1 = kvbf[c + 1];
                float b2 = kvbf[c2], b3 = kvbf[c2 + 1];
                int G = (wnK >> 4) + jp;
                uint4 u;
                u.x = pack2(acc[mt][j][0] + b0, acc[mt][j][1] + b1, u.z);
                u.y = pack2(acc[mt][j + 1][0] + b2, acc[mt][j + 1][1] + b3, u.w);
                sm4[K4_OFF + key0 * 68 + G * 4 + t] = u;
                uint4 v;
                v.x = pack2(acc[mt][j][2] + b0, acc[mt][j][3] + b1, v.z);
                v.y = pack2(acc[mt][j + 1][2] + b2, acc[mt][j + 1][3] + b3, v.w);
                sm4[K4_OFF + (key0 + 8) * 68 + G * 4 + t] = v;
            }
        }
    } else {
        #pragma unroll
        for (int mt = 0; mt < 2; mt++) {
            int ks = mB + mt;
            #pragma unroll
            for (int j = 0; j < 8; j++) {
                int c = wnK - 256 + 8 * j + 2 * t;
                float b0 = kvbf[256 + c], b1 = kvbf[256 + c + 1];
                float v0 = acc[mt][j][0] + b0, v1 = acc[mt][j][1] + b1;
                float v2 = acc[mt][j][2] + b0, v3 = acc[mt][j][3] + b1;
                float o0 = __shfl_xor_sync(0xffffffffu, v0, 4);
                float o1 = __shfl_xor_sync(0xffffffffu, v1, 4);
                float o2 = __shfl_xor_sync(0xffffffffu, v2, 4);
                float o3 = __shfl_xor_sync(0xffffffffu, v3, 4);
                if ((g & 1) == 0) {
                    int tq = g >> 1;
                    uint4 u;
                    u.x = pack2(v0, o0, u.z);
                    u.y = pack2(v2, o2, u.w);
                    sm4[A4_OFF + ks * 1024 + c * 4 + tq] = u;
                    uint4 v;
                    v.x = pack2(v1, o1, v.z);
                    v.y = pack2(v3, o3, v.w);
                    sm4[A4_OFF + ks * 1024 + (c + 1) * 4 + tq] = v;
                }
            }
        }
    }
    __syncthreads();

    // ---- attention: 16 warps = 8 q-blocks x 2 head-groups; O kept in regs ----
    const int qb = w >> 1;
    const int hbase = (w & 1) * 4;
    uint32_t Ohi[4][8], Olo[4][8];

    #pragma unroll
    for (int hh = 0; hh < 4; hh++) {
        const int h = hbase + hh;

        float sacc[8][4];
        #pragma unroll
        for (int j = 0; j < 8; j++) {
            float4 bv = __ldg(&g_b4[((h * 8 + qb) * 8 + j) * 32 + lane]);
            sacc[j][0] = bv.x; sacc[j][1] = bv.y;
            sacc[j][2] = bv.z; sacc[j][3] = bv.w;
        }
        #pragma unroll
        for (int ks = 0; ks < 2; ks++) {
            uint4 Qh = __ldg(&g_q4h[((h * 8 + qb) * 2 + ks) * 32 + lane]);
            uint4 Ql = __ldg(&g_q4l[((h * 8 + qb) * 2 + ks) * 32 + lane]);
            #pragma unroll
            for (int j = 0; j < 8; j++) {
                uint4 K = sm4[K4_OFF + (8 * j + g) * 68 + (h * 2 + ks) * 4 + t];
                mma3(sacc[j], Qh, Ql, K);
            }
        }

        // softmax over 64 keys (rows in 4-lane groups)
        float m0 = -1e30f, m1 = -1e30f;
        #pragma unroll
        for (int j = 0; j < 8; j++) {
            m0 = fmaxf(m0, fmaxf(sacc[j][0], sacc[j][1]));
            m1 = fmaxf(m1, fmaxf(sacc[j][2], sacc[j][3]));
        }
        m0 = fmaxf(m0, __shfl_xor_sync(0xffffffffu, m0, 1));
        m0 = fmaxf(m0, __shfl_xor_sync(0xffffffffu, m0, 2));
        m1 = fmaxf(m1, __shfl_xor_sync(0xffffffffu, m1, 1));
        m1 = fmaxf(m1, __shfl_xor_sync(0xffffffffu, m1, 2));
        float s0 = 0.f, s1 = 0.f;
        #pragma unroll
        for (int j = 0; j < 8; j++) {
            sacc[j][0] = __expf(sacc[j][0] - m0); s0 += sacc[j][0];
            sacc[j][1] = __expf(sacc[j][1] - m0); s0 += sacc[j][1];
            sacc[j][2] = __expf(sacc[j][2] - m1); s1 += sacc[j][2];
            sacc[j][3] = __expf(sacc[j][3] - m1); s1 += sacc[j][3];
        }
        s0 += __shfl_xor_sync(0xffffffffu, s0, 1);
        s0 += __shfl_xor_sync(0xffffffffu, s0, 2);
        s1 += __shfl_xor_sync(0xffffffffu, s1, 1);
        s1 += __shfl_xor_sync(0xffffffffu, s1, 2);
        float inv0 = 1.0f / s0, inv1 = 1.0f / s1;
        #pragma unroll
        for (int j = 0; j < 8; j++) {
            sacc[j][0] *= inv0; sacc[j][1] *= inv0;
            sacc[j][2] *= inv1; sacc[j][3] *= inv1;
        }

        // O = P V (A-fragments repacked from sacc in registers)
        float oacc[4][4];
        #pragma unroll
        for (int j = 0; j < 4; j++)
            #pragma unroll
            for (int e = 0; e < 4; e++) oacc[j][e] = 0.f;

        #pragma unroll
        for (int ks = 0; ks < 4; ks++) {
            uint4 ah, al;
            ah.x = pack2(sacc[2 * ks][0], sacc[2 * ks][1], al.x);
            ah.y = pack2(sacc[2 * ks][2], sacc[2 * ks][3], al.y);
            ah.z = pack2(sacc[2 * ks + 1][0], sacc[2 * ks + 1][1], al.z);
            ah.w = pack2(sacc[2 * ks + 1][2], sacc[2 * ks + 1][3], al.w);
            #pragma unroll
            for (int j = 0; j < 4; j++) {
                uint4 V = sm4[A4_OFF + ks * 1024 + (h * 32 + 8 * j + g) * 4 + t];
                mma3(oacc[j], ah, al, V);
            }
        }

        // pack O into registers (retained across heads)
        #pragma unroll
        for (int jp = 0; jp < 2; jp++) {
            int j = 2 * jp;
            Ohi[hh][jp * 4 + 0] = pack2(oacc[j][0], oacc[j][1], Olo[hh][jp * 4 + 0]);
            Ohi[hh][jp * 4 + 1] = pack2(oacc[j][2], oacc[j][3], Olo[hh][jp * 4 + 1]);
            Ohi[hh][jp * 4 + 2] = pack2(oacc[j + 1][0], oacc[j + 1][1], Olo[hh][jp * 4 + 2]);
            Ohi[hh][jp * 4 + 3] = pack2(oacc[j + 1][2], oacc[j + 1][3], Olo[hh][jp * 4 + 3]);
        }
    }
    __syncthreads();   // all K/V smem reads complete

    // ---- write O fragments into smem A region (a4+k4 reused) ----
    #pragma unroll
    for (int hh = 0; hh < 4; hh++) {
        #pragma unroll
        for (int jp = 0; jp < 2; jp++) {
            int kc = (hbase + hh) * 2 + jp;
            int base = kc * 520 + t * 130 + qb * 16;
            sm4[base + g] = make_uint4(Ohi[hh][jp * 4 + 0], Ohi[hh][jp * 4 + 1],
                                       Ohi[hh][jp * 4 + 2], Ohi[hh][jp * 4 + 3]);
            sm4[base + 8 + g] = make_uint4(Olo[hh][jp * 4 + 0], Olo[hh][jp * 4 + 1],
                                           Olo[hh][jp * 4 + 2], Olo[hh][jp * 4 + 3]);
        }
    }

    // prologue for proj B staging (kc=0)
    {
        #pragma unroll
        for (int k = 0; k < 2; k++) {
            int gi = tid + k * 512;
            int n = gi & 255, tt = gi >> 8;
            cp16(smem_base + (WS4_OFF + tt * 274 + n) * 16, &g_pw4[gi]);
        }
        CP_COMMIT();
    }
    __syncthreads();   // O fragments visible

    // ---- proj phase: out = O @ pw^T + pb ----
    const int wmP = (w >> 2) * 32;
    const int wnP = (w & 3) * 64;
    const int qB  = (w >> 2) * 2;

    float pacc[2][8][4];
    #pragma unroll
    for (int mt = 0; mt < 2; mt++)
        #pragma unroll
        for (int j = 0; j < 8; j++)
            #pragma unroll
            for (int e = 0; e < 4; e++) pacc[mt][j][e] = 0.f;

    for (int kc = 0; kc < 16; kc++) {
        if (kc + 1 < 16) {
            int bufn = (kc + 1) & 1;
            #pragma unroll
            for (int k = 0; k < 2; k++) {
                int gi = tid + k * 512;
                int n = gi & 255, tt = gi >> 8;
                cp16(smem_base + (WS4_OFF + bufn * 1096 + tt * 274 + n) * 16,
                     &g_pw4[(kc + 1) * 1024 + gi]);
            }
            CP_COMMIT();
            CP_WAIT1();
        } else {
            CP_WAIT0();
        }
        __syncthreads();

        int bufc = WS4_OFF + (kc & 1) * 1096;
        uint4 Ah[2], Al[2];
        #pragma unroll
        for (int mt = 0; mt < 2; mt++) {
            int ai = kc * 520 + t * 130 + (qB + mt) * 16;
            Ah[mt] = sm4[ai + g];
            Al[mt] = sm4[ai + 8 + g];
        }
        #pragma unroll
        for (int j = 0; j < 8; j++) {
            uint4 B = sm4[bufc + t * 274 + wnP + 8 * j + g];
            mma3(pacc[0][j], Ah[0], Al[0], B);
            mma3(pacc[1][j], Ah[1], Al[1], B);
        }
    }

    // epilogue
    #pragma unroll
    for (int j = 0; j < 8; j++) {
        int oc = wnP + 8 * j + 2 * t;
        float b0 = __ldg(pb + oc), b1 = __ldg(pb + oc + 1);
        #pragma unroll
        for (int mt = 0; mt < 2; mt++) {
            size_t r = (size_t)bw * 128 + wmP + mt * 16 + g;
            *(float2*)(out + r * 256 + oc) =
                make_float2(pacc[mt][j][0] + b0, pacc[mt][j][1] + b1);
            *(float2*)(out + (r + 8) * 256 + oc) =
                make_float2(pacc[mt][j][2] + b0, pacc[mt][j][3] + b1);
        }
    }
}

// ---------------- launch ----------------
static const float* find_by_size(void* const* d_in, const int* in_sizes,
                                 int n_in, int want) {
    for (int i = 0; i < n_in; i++)
        if (in_sizes[i] == want) return (const float*)d_in[i];
    return nullptr;
}

extern "C" void kernel_launch(void* const* d_in, const int* in_sizes, int n_in,
                              void* d_out, int out_size) {
    const float* embeds = find_by_size(d_in, in_sizes, n_in, 128 * 256);
    const float* x      = find_by_size(d_in, in_sizes, n_in, 2 * 256 * 256 * 256);
    const float* rpb    = find_by_size(d_in, in_sizes, n_in, 225 * 8);
    const float* kvw    = find_by_size(d_in, in_sizes, n_in, 512 * 256);
    const float* kvb    = find_by_size(d_in, in_sizes, n_in, 512);
    const float* pw     = find_by_size(d_in, in_sizes, n_in, 256 * 256);
    const float* pb     = find_by_size(d_in, in_sizes, n_in, 256);
    float* out = (float*)d_out;

    prep_q4<<<16, 256>>>(embeds);
    prep_b4<<<64, 256>>>(rpb);
    prep_w4<<<192, 256>>>(kvw, pw);

    cudaFuncSetAttribute(win_attn,
                         cudaFuncAttributeMaxDynamicSharedMemorySize, SMEM_BYTES);
    win_attn<<<NWIN, 512, SMEM_BYTES>>>(x, kvb, pb, out);
}